// round 12
// baseline (speedup 1.0000x reference)
#include <cuda_runtime.h>
#include <cuda_fp16.h>
#include <math.h>
#include <stdint.h>

#define N_NODES 40000
#define N_PAD   40064
#define N_EDGES 640000
#define CCH 128
#define NQKV 384

// mega_prep block ranges
#define BIASB  3
#define CVTB   10016           // N_PAD*64 / 256 exact
#define PREPB  544             // 139264 / 256
#define INITB  157
#define MEGA_BLKS (BIASB + CVTB + PREPB + INITB)

// combined qkv0 + CSR kernel
#define CSRB      157          // persistent CSR blocks (all co-resident in wave 1)
#define QKV_BLKS  1875         // 3 x 625
#define COMB_BLKS (CSRB + QKV_BLKS)

// ---------------- device scratch ----------------
__device__ __half g_a16[(size_t)N_PAD * CCH];
__device__ __half g_qkv16[(size_t)N_PAD * NQKV];
__device__ __half g_agg16[(size_t)N_PAD * CCH];
__device__ float  g_h1[(size_t)N_NODES * CCH];
__device__ int    g_rowptr[N_NODES + 1];
__device__ int    g_colsrc[N_EDGES];
__device__ int    g_counts[N_NODES];
__device__ int    g_fill[N_NODES];
__device__ int    g_bsums[CSRB];
__device__ float  g_bqkv[2 * NQKV];
__device__ __half g_bt[139264];
__device__ int    g_use64;
__device__ int    g_bcnt;
__device__ volatile int g_bsense;

// ---------------- helpers ----------------
__device__ __forceinline__ uint32_t smem_u32(const void* p) {
    uint32_t a;
    asm("{ .reg .u64 t; cvta.to.shared.u64 t, %1; cvt.u32.u64 %0, t; }" : "=r"(a) : "l"(p));
    return a;
}
__device__ __forceinline__ void cp_async16(uint32_t dst, const void* src) {
    asm volatile("cp.async.ca.shared.global [%0], [%1], 16;" :: "r"(dst), "l"(src));
}
__device__ __forceinline__ void cp_async_wait_all() {
    asm volatile("cp.async.commit_group;");
    asm volatile("cp.async.wait_group 0;");
}
__device__ __forceinline__ int ld_idx(const void* ei, long long pos, int use64) {
    if (use64) return (int)((const long long*)ei)[pos];
    return ((const int*)ei)[pos];
}
__device__ __forceinline__ float gelu_tanh(float x) {
    float x3 = x * x * x;
    return 0.5f * x * (1.0f + tanhf(0.7978845608028654f * (x + 0.044715f * x3)));
}
__device__ __forceinline__ void ldsm4(uint32_t* r, uint32_t addr) {
    asm volatile("ldmatrix.sync.aligned.m8n8.x4.shared.b16 {%0,%1,%2,%3}, [%4];"
        : "=r"(r[0]), "=r"(r[1]), "=r"(r[2]), "=r"(r[3]) : "r"(addr));
}
__device__ __forceinline__ void mma16816(float* c, const uint32_t* a, uint32_t b0, uint32_t b1) {
    asm volatile("mma.sync.aligned.m16n8k16.row.col.f32.f16.f16.f32 "
        "{%0,%1,%2,%3}, {%4,%5,%6,%7}, {%8,%9}, {%0,%1,%2,%3};"
        : "+f"(c[0]), "+f"(c[1]), "+f"(c[2]), "+f"(c[3])
        : "r"(a[0]), "r"(a[1]), "r"(a[2]), "r"(a[3]), "r"(b0), "r"(b1));
}

// ---------------- mega_prep: bias | cvt_x | prep_b(direct) | init+detect ----------------
__global__ __launch_bounds__(256)
void mega_prep(const float* __restrict__ x, const void* ei,
               const float* Wk, const float* bk, const float* Wq, const float* bq,
               const float* Wv, const float* bv,
               const float* a_rel, const float* m_rel, const float* p_rel,
               const float* aW, const float* fcW) {
    int b = blockIdx.x, tid = threadIdx.x;
    if (b < BIASB) {
        int idx = b * 256 + tid;
        if (idx < 768) {
            int l = idx / NQKV, c = idx % NQKV;
            int t = c >> 7, cc = c & 127, h = cc >> 4, eo = cc & 15;
            float bias;
            if (t == 0) bias = bq[l * 128 + cc] * p_rel[l * 8 + h] * 0.25f;
            else {
                const float* bm = (t == 1) ? bk : bv;
                const float* R  = (t == 1) ? a_rel : m_rel;
                float sb = 0.f;
                #pragma unroll
                for (int d = 0; d < 16; ++d)
                    sb += bm[l * 128 + h * 16 + d] * R[((l * 8 + h) * 16 + d) * 16 + eo];
                bias = sb;
            }
            g_bqkv[l * NQKV + c] = bias;
        }
        return;
    }
    b -= BIASB;
    if (b < CVTB) {
        int i = b * 256 + tid;
        if (i < N_NODES * 64) {
            float2 v = ((const float2*)x)[i];
            ((__half2*)g_a16)[i] = __floats2half2_rn(v.x, v.y);
        } else {
            ((__half2*)g_a16)[i] = __floats2half2_rn(0.f, 0.f);
        }
        return;
    }
    b -= CVTB;
    if (b < PREPB) {
        int e = b * 256 + tid;
        float val;
        if (e < 131072) {
            int tile = e >> 14, within = e & 16383;
            int nn = within >> 7, k = within & 127;
            int l = tile >> 2, t = tile & 3;
            if (t == 0)      val = Wq[(size_t)l * 16384 + k * 128 + nn] * p_rel[l * 8 + (nn >> 4)] * 0.25f;
            else if (t == 3) val = aW[(size_t)l * 16384 + k * 128 + nn];
            else {
                const float* Wm = (t == 1) ? Wk : Wv;
                const float* R  = (t == 1) ? a_rel : m_rel;
                int h = nn >> 4, eo = nn & 15;
                float s = 0.f;
                #pragma unroll
                for (int d = 0; d < 16; ++d)
                    s += Wm[(size_t)l * 16384 + k * 128 + h * 16 + d] * R[((l * 8 + h) * 16 + d) * 16 + eo];
                val = s;
            }
        } else {
            int e2 = e - 131072;
            int nn = e2 >> 7, k = e2 & 127;
            val = fcW[k * 64 + nn];
        }
        g_bt[e] = __float2half(val);
        return;
    }
    b -= PREPB;
    {
        int gi = b * 256 + tid;
        if (gi < N_NODES) { g_counts[gi] = 0; g_fill[gi] = 0; }
        if (b == 0) {
            __shared__ int any;
            if (tid == 0) any = 0;
            __syncthreads();
            int v = 0;
            const int* w = (const int*)ei;
            for (int i = tid; i < 2048; i += 256) v |= w[2 * i + 1];
            if (v) atomicOr(&any, 1);
            __syncthreads();
            if (tid == 0) g_use64 = (any == 0) ? 1 : 0;
        }
    }
}

// ---------------- gemm core: CTA 64m x NTn, 4 warps; optional h->smem park ----------------
template<int NT>
__device__ __forceinline__ void gemm_core(char* sm,
    const __half* __restrict__ A16, const __half* __restrict__ btile,
    const float* __restrict__ bias,
    float* C32, int c32s, __half* C16, int c16s,
    int mode, const float* skip, const float* gate, int m0, int park_h) {
    constexpr int NB2 = NT / 32;
    constexpr uint32_t BOFF = 64 * 272;
    uint32_t sbase = smem_u32(sm);
    int tid = threadIdx.x, wid = tid >> 5, lane = tid & 31;

    const __half* asrc = A16 + (size_t)m0 * 128;
    #pragma unroll
    for (int i = tid; i < 1024; i += 128) {
        int row = i >> 4, kc = i & 15;
        cp_async16(sbase + row * 272 + kc * 16, asrc + row * 128 + kc * 8);
    }
    #pragma unroll
    for (int i = tid; i < NT * 16; i += 128) {
        int row = i >> 4, kc = i & 15;
        cp_async16(sbase + BOFF + row * 272 + kc * 16, btile + row * 128 + kc * 8);
    }
    cp_async_wait_all();
    __syncthreads();

    int wm = wid & 1, wn = wid >> 1;
    uint32_t arowoff[2];
    #pragma unroll
    for (int mb = 0; mb < 2; ++mb) {
        int arow = wm * 32 + mb * 16 + (lane & 15);
        arowoff[mb] = (uint32_t)arow * 272u + (uint32_t)(lane & 16);
    }
    uint32_t browoff[NB2];
    #pragma unroll
    for (int nb2 = 0; nb2 < NB2; ++nb2) {
        int brow = wn * (NT / 2) + nb2 * 16 + (lane & 7) + ((lane & 16) >> 1);
        browoff[nb2] = (uint32_t)brow * 272u + (uint32_t)((lane & 8) << 1);
    }

    float acc[2][2 * NB2][4];
    #pragma unroll
    for (int mb = 0; mb < 2; ++mb)
        #pragma unroll
        for (int nb = 0; nb < 2 * NB2; ++nb)
            #pragma unroll
            for (int j = 0; j < 4; ++j) acc[mb][nb][j] = 0.0f;

    #pragma unroll
    for (int ks = 0; ks < 8; ++ks) {
        uint32_t kb = (uint32_t)ks * 32u;
        uint32_t a[2][4];
        ldsm4(a[0], sbase + arowoff[0] + kb);
        ldsm4(a[1], sbase + arowoff[1] + kb);
        #pragma unroll
        for (int nb2 = 0; nb2 < NB2; ++nb2) {
            uint32_t bb[4];
            ldsm4(bb, sbase + BOFF + browoff[nb2] + kb);
            mma16816(acc[0][2 * nb2],     a[0], bb[0], bb[1]);
            mma16816(acc[1][2 * nb2],     a[1], bb[0], bb[1]);
            mma16816(acc[0][2 * nb2 + 1], a[0], bb[2], bb[3]);
            mma16816(acc[1][2 * nb2 + 1], a[1], bb[2], bb[3]);
        }
    }

    if (park_h) __syncthreads();

    float beta = 0.f, ombeta = 0.f;
    if (mode == 1) {
        float g = gate[0];
        beta = 1.f / (1.f + expf(-g));
        ombeta = 1.f - beta;
    }
    int quad = lane >> 2, qt = lane & 3;
    int n0 = wn * (NT / 2);
    #pragma unroll
    for (int mb = 0; mb < 2; ++mb)
        #pragma unroll
        for (int half = 0; half < 2; ++half) {
            int lr = wm * 32 + mb * 16 + quad + half * 8;
            int grow = m0 + lr;
            #pragma unroll
            for (int nb = 0; nb < 2 * NB2; ++nb) {
                int col = n0 + nb * 8 + qt * 2;
                float v0 = acc[mb][nb][2 * half + 0] + bias[col + 0];
                float v1 = acc[mb][nb][2 * half + 1] + bias[col + 1];
                if (mode == 1) {
                    float2 sv = *(const float2*)(skip + (size_t)grow * 128 + col);
                    v0 = fmaxf(beta * v0 + ombeta * sv.x, 0.f);
                    v1 = fmaxf(beta * v1 + ombeta * sv.y, 0.f);
                }
                if (C32) {
                    float2 o; o.x = v0; o.y = v1;
                    *(float2*)(C32 + (size_t)grow * c32s + col) = o;
                }
                if (C16)
                    *(__half2*)(C16 + (size_t)grow * c16s + col) = __floats2half2_rn(v0, v1);
                if (park_h)
                    *(__half2*)(sm + lr * 272 + col * 2) = __floats2half2_rn(v0, v1);
            }
        }
}

// ---------------- combined: layer-0 QKV gemm blocks + persistent CSR blocks ----------------
// CSR blocks (0..CSRB-1) build the CSR with an internal grid barrier; gemm blocks
// never wait. No data dependency between roles. All CSRB blocks are co-resident
// in wave 1 (4 blocks/SM x 148 SMs = 592 slots >= CSRB, lowest blockIdx first).
__global__ __launch_bounds__(128, 4)
void qkv_csr_kernel(const void* ei) {
    extern __shared__ char sm[];
    if (blockIdx.x >= CSRB) {
        int b = blockIdx.x - CSRB;
        int bx = b % 3, by = b / 3;
        gemm_core<128>(sm, g_a16, g_bt + (size_t)bx * 16384,
                       g_bqkv + bx * 128,
                       nullptr, 0, g_qkv16 + bx * 128, NQKV,
                       0, nullptr, nullptr, by * 64, 0);
        return;
    }
    // ---- CSR role ----
    int b = blockIdx.x, tid = threadIdx.x;
    int lane = tid & 31, w = tid >> 5;
    __shared__ int lsense;
    __shared__ int wtot[4], woff[4], btot;
    if (tid == 0) lsense = g_bsense;   // entry sense, read before any barrier
    __syncthreads();
    auto gbar = [&]() {
        __threadfence();
        __syncthreads();
        if (tid == 0) {
            int ns = lsense ^ 1;
            lsense = ns;
            if (atomicAdd(&g_bcnt, 1) == CSRB - 1) {
                g_bcnt = 0;
                __threadfence();
                g_bsense = ns;
            } else {
                while (g_bsense != ns) __nanosleep(64);
            }
        }
        __syncthreads();
    };
    int use64 = g_use64;
    // P1: histogram
    for (int e = b * 128 + tid; e < N_EDGES; e += CSRB * 128)
        atomicAdd(&g_counts[ld_idx(ei, (long long)N_EDGES + e, use64)], 1);
    gbar();
    // P2: per-block chunk scan (256 nodes per block, 2 tiles of 128)
    int base = b * 256;
    int carry = 0;
    #pragma unroll
    for (int t = 0; t < 2; ++t) {
        int idx = base + t * 128 + tid;
        int v = (idx < N_NODES) ? __ldcg(&g_counts[idx]) : 0;
        int x = v;
        #pragma unroll
        for (int o = 1; o < 32; o <<= 1) {
            int s = __shfl_up_sync(0xffffffffu, x, o);
            if (lane >= o) x += s;
        }
        if (lane == 31) wtot[w] = x;
        __syncthreads();
        if (tid < 4) {
            int ww = wtot[tid]; int y = ww;
            #pragma unroll
            for (int o = 1; o < 4; o <<= 1) {
                int s = __shfl_up_sync(0xFu, y, o);
                if (tid >= o) y += s;
            }
            woff[tid] = y - ww;
            if (tid == 3) btot = y;
        }
        __syncthreads();
        if (idx < N_NODES) g_rowptr[idx] = carry + x + woff[w] - v;   // exclusive
        carry += btot;
        __syncthreads();
    }
    if (tid == 0) g_bsums[b] = carry;
    gbar();
    // P3: block 0, warp 0 scans block sums
    if (b == 0 && tid < 32) {
        int c = 0;
        for (int bs = 0; bs < CSRB; bs += 32) {
            int idx = bs + tid;
            int v = (idx < CSRB) ? __ldcg(&g_bsums[idx]) : 0;
            int x = v;
            #pragma unroll
            for (int o = 1; o < 32; o <<= 1) {
                int s = __shfl_up_sync(0xffffffffu, x, o);
                if (tid >= o) x += s;
            }
            if (idx < CSRB) g_bsums[idx] = c + x - v;
            c += __shfl_sync(0xffffffffu, x, 31);
        }
        if (tid == 0) g_rowptr[N_NODES] = c;
    }
    gbar();
    // P4: add block offsets
    {
        int off = __ldcg(&g_bsums[b]);
        #pragma unroll
        for (int t = 0; t < 2; ++t) {
            int idx = base + t * 128 + tid;
            if (idx < N_NODES) g_rowptr[idx] = __ldcg(&g_rowptr[idx]) + off;
        }
    }
    gbar();
    // P5: scatter
    for (int e = b * 128 + tid; e < N_EDGES; e += CSRB * 128) {
        int d = ld_idx(ei, (long long)N_EDGES + e, use64);
        int s = ld_idx(ei, e, use64);
        g_colsrc[__ldcg(&g_rowptr[d]) + atomicAdd(&g_fill[d], 1)] = s;
    }
}

// ---------------- standalone GEMM kernels ----------------
__global__ __launch_bounds__(128, 4)
void qkv_kernel(int l) {
    extern __shared__ char sm[];
    int bx = blockIdx.x;
    gemm_core<128>(sm, g_a16, g_bt + (size_t)(l * 4 + bx) * 16384,
                   g_bqkv + l * NQKV + bx * 128,
                   nullptr, 0, g_qkv16 + bx * 128, NQKV,
                   0, nullptr, nullptr, blockIdx.y * 64, 0);
}

__global__ __launch_bounds__(128, 4)
void aw_kernel(int l, const float* __restrict__ ab,
               const float* __restrict__ skipsrc, const float* __restrict__ gate) {
    extern __shared__ char sm[];
    gemm_core<128>(sm, g_agg16, g_bt + (size_t)(l * 4 + 3) * 16384, ab,
                   (float*)g_h1, CCH, g_a16, CCH,
                   1, skipsrc, gate, blockIdx.y * 64, 0);
}

// aw layer-1 with fused fc
#define FC_OFF 52224
__global__ __launch_bounds__(128, 3)
void aw_fc_kernel(const float* __restrict__ ab,
                  const float* __restrict__ skipsrc, const float* __restrict__ gate,
                  const float* __restrict__ fcb, float* __restrict__ out) {
    extern __shared__ char sm[];
    uint32_t sbase = smem_u32(sm);
    int tid = threadIdx.x, wid = tid >> 5, lane = tid & 31;
    int m0 = blockIdx.y * 64;

    {
        const __half* fsrc = g_bt + (size_t)8 * 16384;
        #pragma unroll
        for (int i = tid; i < 1024; i += 128) {
            int row = i >> 4, kc = i & 15;
            cp_async16(sbase + FC_OFF + row * 272 + kc * 16, fsrc + row * 128 + kc * 8);
        }
    }
    gemm_core<128>(sm, g_agg16, g_bt + (size_t)7 * 16384, ab,
                   nullptr, 0, nullptr, 0, 1, skipsrc, gate, m0, 1);
    __syncthreads();

    int wm = wid & 1, wn = wid >> 1;
    uint32_t arowoff[2];
    #pragma unroll
    for (int mb = 0; mb < 2; ++mb) {
        int arow = wm * 32 + mb * 16 + (lane & 15);
        arowoff[mb] = (uint32_t)arow * 272u + (uint32_t)(lane & 16);
    }
    uint32_t browoff[2];
    #pragma unroll
    for (int nb2 = 0; nb2 < 2; ++nb2) {
        int brow = wn * 32 + nb2 * 16 + (lane & 7) + ((lane & 16) >> 1);
        browoff[nb2] = (uint32_t)brow * 272u + (uint32_t)((lane & 8) << 1);
    }
    float acc[2][4][4];
    #pragma unroll
    for (int mb = 0; mb < 2; ++mb)
        #pragma unroll
        for (int nb = 0; nb < 4; ++nb)
            #pragma unroll
            for (int j = 0; j < 4; ++j) acc[mb][nb][j] = 0.0f;
    #pragma unroll
    for (int ks = 0; ks < 8; ++ks) {
        uint32_t kb = (uint32_t)ks * 32u;
        uint32_t a[2][4];
        ldsm4(a[0], sbase + arowoff[0] + kb);
        ldsm4(a[1], sbase + arowoff[1] + kb);
        #pragma unroll
        for (int nb2 = 0; nb2 < 2; ++nb2) {
            uint32_t bb[4];
            ldsm4(bb, sbase + FC_OFF + browoff[nb2] + kb);
            mma16816(acc[0][2 * nb2],     a[0], bb[0], bb[1]);
            mma16816(acc[1][2 * nb2],     a[1], bb[0], bb[1]);
            mma16816(acc[0][2 * nb2 + 1], a[0], bb[2], bb[3]);
            mma16816(acc[1][2 * nb2 + 1], a[1], bb[2], bb[3]);
        }
    }
    int quad = lane >> 2, qt = lane & 3;
    int n0 = wn * 32;
    #pragma unroll
    for (int mb = 0; mb < 2; ++mb)
        #pragma unroll
        for (int half = 0; half < 2; ++half) {
            int grow = m0 + wm * 32 + mb * 16 + quad + half * 8;
            #pragma unroll
            for (int nb = 0; nb < 4; ++nb) {
                int col = n0 + nb * 8 + qt * 2;
                float2 o;
                o.x = acc[mb][nb][2 * half + 0] + fcb[col + 0];
                o.y = acc[mb][nb][2 * half + 1] + fcb[col + 1];
                *(float2*)(out + (size_t)grow * 64 + col) = o;
            }
        }
}

// ---------------- edge kernel: 2 edges/warp-iter, 16 lanes/edge, 2x pipelined ----------------
__global__ __launch_bounds__(256)
void edge_kernel() {
    int tid = threadIdx.x, wid = tid >> 5, lane = tid & 31;
    int node = blockIdx.x * 8 + wid;
    int sub = lane >> 4, j = lane & 15;

    float q[8];
    {
        uint4 qraw = *(const uint4*)(g_qkv16 + (size_t)node * NQKV + 8 * j);
        const __half2* qh = (const __half2*)&qraw;
        #pragma unroll
        for (int t = 0; t < 4; ++t) {
            q[2 * t]     = __low2float(qh[t]);
            q[2 * t + 1] = __high2float(qh[t]);
        }
    }
    int p0 = g_rowptr[node], p1 = g_rowptr[node + 1];
    float s = 0.f;
    float acc[8];
    #pragma unroll
    for (int t = 0; t < 8; ++t) acc[t] = 0.f;

    int iters = (p1 - p0 + 1) >> 1;
    for (int it = 0; it < iters; it += 2) {
        int pA = p0 + 2 * it + sub;
        int pB = pA + 2;
        bool vA = pA < p1;
        bool vB = (it + 1 < iters) && (pB < p1);
        int snA = g_colsrc[vA ? pA : p0];
        int snB = g_colsrc[vB ? pB : p0];
        const __half* baseA = g_qkv16 + (size_t)snA * NQKV;
        const __half* baseB = g_qkv16 + (size_t)snB * NQKV;
        uint4 kA = *(const uint4*)(baseA + CCH + 8 * j);
        uint4 vA_ = *(const uint4*)(baseA + 2 * CCH + 8 * j);
        uint4 kB = *(const uint4*)(baseB + CCH + 8 * j);
        uint4 vB_ = *(const uint4*)(baseB + 2 * CCH + 8 * j);
        {
            const __half2* kh = (const __half2*)&kA;
            const __half2* vh = (const __half2*)&vA_;
            float d = 0.f;
            #pragma unroll
            for (int t = 0; t < 4; ++t)
                d += q[2 * t] * __low2float(kh[t]) + q[2 * t + 1] * __high2float(kh[t]);
            d += __shfl_xor_sync(0xffffffffu, d, 1);
            float e = vA ? __expf(d) : 0.f;
            s += e;
            #pragma unroll
            for (int t = 0; t < 4; ++t) {
                acc[2 * t]     = fmaf(e, __low2float(vh[t]), acc[2 * t]);
                acc[2 * t + 1] = fmaf(e, __high2float(vh[t]), acc[2 * t + 1]);
            }
        }
        {
            const __half2* kh = (const __half2*)&kB;
            const __half2* vh = (const __half2*)&vB_;
            float d = 0.f;
            #pragma unroll
            for (int t = 0; t < 4; ++t)
                d += q[2 * t] * __low2float(kh[t]) + q[2 * t + 1] * __high2float(kh[t]);
            d += __shfl_xor_sync(0xffffffffu, d, 1);
            float e = vB ? __expf(d) : 0.f;
            s += e;
            #pragma unroll
            for (int t = 0; t < 4; ++t) {
                acc[2 * t]     = fmaf(e, __low2float(vh[t]), acc[2 * t]);
                acc[2 * t + 1] = fmaf(e, __high2float(vh[t]), acc[2 * t + 1]);
            }
        }
    }

    s += __shfl_xor_sync(0xffffffffu, s, 16);
    #pragma unroll
    for (int t = 0; t < 8; ++t)
        acc[t] += __shfl_xor_sync(0xffffffffu, acc[t], 16);

    if (sub == 0) {
        float inv = 1.f / (s + 1e-16f);
        __half2 o[4];
        #pragma unroll
        for (int t = 0; t < 4; ++t)
            o[t] = __floats2half2_rn(gelu_tanh(acc[2 * t] * inv),
                                     gelu_tanh(acc[2 * t + 1] * inv));
        *(uint4*)(g_agg16 + (size_t)node * CCH + 8 * j) = *(uint4*)o;
    }
}

// ---------------- host launch ----------------
#define SMEM_G128 (64 * 272 + 128 * 272)       // 52224
#define SMEM_AWFC (52224 + 64 * 272)           // 69632

extern "C" void kernel_launch(void* const* d_in, const int* in_sizes, int n_in,
                              void* d_out, int out_size) {
    const float* x    = (const float*)d_in[0];
    const void*  ei   = d_in[1];
    const float* Wk   = (const float*)d_in[2];
    const float* bk   = (const float*)d_in[3];
    const float* Wq   = (const float*)d_in[4];
    const float* bq   = (const float*)d_in[5];
    const float* Wv   = (const float*)d_in[6];
    const float* bv   = (const float*)d_in[7];
    const float* a_rel = (const float*)d_in[8];
    const float* m_rel = (const float*)d_in[9];
    const float* p_rel = (const float*)d_in[10];
    const float* skip  = (const float*)d_in[11];
    const float* aW    = (const float*)d_in[12];
    const float* ab    = (const float*)d_in[13];
    const float* fcW   = (const float*)d_in[14];
    const float* fcb   = (const float*)d_in[15];
    float* out = (float*)d_out;

    float* p_h1;
    cudaGetSymbolAddress((void**)&p_h1, g_h1);

    cudaFuncSetAttribute(qkv_csr_kernel, cudaFuncAttributeMaxDynamicSharedMemorySize, SMEM_G128);
    cudaFuncSetAttribute(qkv_kernel,     cudaFuncAttributeMaxDynamicSharedMemorySize, SMEM_G128);
    cudaFuncSetAttribute(aw_kernel,      cudaFuncAttributeMaxDynamicSharedMemorySize, SMEM_G128);
    cudaFuncSetAttribute(aw_fc_kernel,   cudaFuncAttributeMaxDynamicSharedMemorySize, SMEM_AWFC);

    // #1 mega_prep (bias | cvt_x | prep_b | init+detect)
    mega_prep<<<MEGA_BLKS, 256>>>(x, ei, Wk, bk, Wq, bq, Wv, bv,
                                  a_rel, m_rel, p_rel, aW, fcW);
    // #2 combined: layer-0 QKV gemm + full CSR build (overlapped, independent roles)
    qkv_csr_kernel<<<COMB_BLKS, 128, SMEM_G128>>>(ei);
    // #3.. rest of the network
    edge_kernel<<<5000, 256>>>();
    aw_kernel<<<dim3(1, 625), 128, SMEM_G128>>>(0, ab, x, skip);
    qkv_kernel<<<dim3(3, 625), 128, SMEM_G128>>>(1);
    edge_kernel<<<5000, 256>>>();
    aw_fc_kernel<<<dim3(1, 625), 128, SMEM_AWFC>>>(ab + CCH, p_h1, skip + 1, fcb, out);
}

// round 13
// speedup vs baseline: 1.0884x; 1.0884x over previous
#include <cuda_runtime.h>
#include <cuda_fp16.h>
#include <math.h>
#include <stdint.h>

#define N_NODES 40000
#define N_PAD   40064
#define N_EDGES 640000
#define CCH 128
#define NQKV 384
#define NB_SCAN 157

// mega_prep block ranges
#define BIASB  3
#define CVTB   10016           // N_PAD*64 / 256 exact
#define PREPB  544             // 139264 / 256
#define INITB  157
#define MEGA_BLKS (BIASB + CVTB + PREPB + INITB)

// ---------------- device scratch ----------------
__device__ __half g_a16[(size_t)N_PAD * CCH];       // layer A input; holds h1 (fp16) after aw0
__device__ __half g_qkv16[(size_t)N_PAD * NQKV];
__device__ __half g_agg16[(size_t)N_PAD * CCH];
__device__ int    g_rowptr[N_NODES + 1];
__device__ int    g_colsrc[N_EDGES];
__device__ int    g_counts[N_NODES];
__device__ int    g_fill[N_NODES];
__device__ int    g_bsums[256];
__device__ float  g_bqkv[2 * NQKV];
__device__ __half g_bt[139264];
__device__ int    g_use64;

// ---------------- helpers ----------------
__device__ __forceinline__ uint32_t smem_u32(const void* p) {
    uint32_t a;
    asm("{ .reg .u64 t; cvta.to.shared.u64 t, %1; cvt.u32.u64 %0, t; }" : "=r"(a) : "l"(p));
    return a;
}
__device__ __forceinline__ void cp_async16(uint32_t dst, const void* src) {
    asm volatile("cp.async.ca.shared.global [%0], [%1], 16;" :: "r"(dst), "l"(src));
}
__device__ __forceinline__ void cp_async_wait_all() {
    asm volatile("cp.async.commit_group;");
    asm volatile("cp.async.wait_group 0;");
}
__device__ __forceinline__ int ld_idx(const void* ei, long long pos) {
    if (g_use64) return (int)((const long long*)ei)[pos];
    return ((const int*)ei)[pos];
}
__device__ __forceinline__ float gelu_tanh(float x) {
    float x3 = x * x * x;
    return 0.5f * x * (1.0f + tanhf(0.7978845608028654f * (x + 0.044715f * x3)));
}
__device__ __forceinline__ void ldsm4(uint32_t* r, uint32_t addr) {
    asm volatile("ldmatrix.sync.aligned.m8n8.x4.shared.b16 {%0,%1,%2,%3}, [%4];"
        : "=r"(r[0]), "=r"(r[1]), "=r"(r[2]), "=r"(r[3]) : "r"(addr));
}
__device__ __forceinline__ void mma16816(float* c, const uint32_t* a, uint32_t b0, uint32_t b1) {
    asm volatile("mma.sync.aligned.m16n8k16.row.col.f32.f16.f16.f32 "
        "{%0,%1,%2,%3}, {%4,%5,%6,%7}, {%8,%9}, {%0,%1,%2,%3};"
        : "+f"(c[0]), "+f"(c[1]), "+f"(c[2]), "+f"(c[3])
        : "r"(a[0]), "r"(a[1]), "r"(a[2]), "r"(a[3]), "r"(b0), "r"(b1));
}

// ---------------- mega_prep: bias | cvt_x | prep_b(direct) | init+detect ----------------
__global__ __launch_bounds__(256)
void mega_prep(const float* __restrict__ x, const void* ei,
               const float* Wk, const float* bk, const float* Wq, const float* bq,
               const float* Wv, const float* bv,
               const float* a_rel, const float* m_rel, const float* p_rel,
               const float* aW, const float* fcW) {
    int b = blockIdx.x, tid = threadIdx.x;
    if (b < BIASB) {
        int idx = b * 256 + tid;
        if (idx < 768) {
            int l = idx / NQKV, c = idx % NQKV;
            int t = c >> 7, cc = c & 127, h = cc >> 4, eo = cc & 15;
            float bias;
            if (t == 0) bias = bq[l * 128 + cc] * p_rel[l * 8 + h] * 0.25f;
            else {
                const float* bm = (t == 1) ? bk : bv;
                const float* R  = (t == 1) ? a_rel : m_rel;
                float sb = 0.f;
                #pragma unroll
                for (int d = 0; d < 16; ++d)
                    sb += bm[l * 128 + h * 16 + d] * R[((l * 8 + h) * 16 + d) * 16 + eo];
                bias = sb;
            }
            g_bqkv[l * NQKV + c] = bias;
        }
        return;
    }
    b -= BIASB;
    if (b < CVTB) {
        int i = b * 256 + tid;
        if (i < N_NODES * 64) {
            float2 v = ((const float2*)x)[i];
            ((__half2*)g_a16)[i] = __floats2half2_rn(v.x, v.y);
        } else {
            ((__half2*)g_a16)[i] = __floats2half2_rn(0.f, 0.f);
        }
        return;
    }
    b -= CVTB;
    if (b < PREPB) {
        int e = b * 256 + tid;
        float val;
        if (e < 131072) {
            int tile = e >> 14, within = e & 16383;
            int nn = within >> 7, k = within & 127;
            int l = tile >> 2, t = tile & 3;
            if (t == 0)      val = Wq[(size_t)l * 16384 + k * 128 + nn] * p_rel[l * 8 + (nn >> 4)] * 0.25f;
            else if (t == 3) val = aW[(size_t)l * 16384 + k * 128 + nn];
            else {
                const float* Wm = (t == 1) ? Wk : Wv;
                const float* R  = (t == 1) ? a_rel : m_rel;
                int h = nn >> 4, eo = nn & 15;
                float s = 0.f;
                #pragma unroll
                for (int d = 0; d < 16; ++d)
                    s += Wm[(size_t)l * 16384 + k * 128 + h * 16 + d] * R[((l * 8 + h) * 16 + d) * 16 + eo];
                val = s;
            }
        } else {
            int e2 = e - 131072;
            int nn = e2 >> 7, k = e2 & 127;
            val = fcW[k * 64 + nn];
        }
        g_bt[e] = __float2half(val);
        return;
    }
    b -= PREPB;
    {
        int gi = b * 256 + tid;
        if (gi < N_NODES) { g_counts[gi] = 0; g_fill[gi] = 0; }
        if (b == 0) {
            __shared__ int any;
            if (tid == 0) any = 0;
            __syncthreads();
            int v = 0;
            const int* w = (const int*)ei;
            for (int i = tid; i < 2048; i += 256) v |= w[2 * i + 1];
            if (v) atomicOr(&any, 1);
            __syncthreads();
            if (tid == 0) g_use64 = (any == 0) ? 1 : 0;
        }
    }
}

// ---------------- CSR build ----------------
__global__ void hist_kernel(const void* ei) {
    int e = blockIdx.x * blockDim.x + threadIdx.x;
    if (e < N_EDGES) atomicAdd(&g_counts[ld_idx(ei, (long long)N_EDGES + e)], 1);
}

__global__ __launch_bounds__(256) void scan1_kernel() {
    __shared__ int wtot[8], woff[8];
    int tid = threadIdx.x;
    int gi = blockIdx.x * 256 + tid;
    int v = (gi < N_NODES) ? g_counts[gi] : 0;
    int x = v;
    #pragma unroll
    for (int o = 1; o < 32; o <<= 1) {
        int t = __shfl_up_sync(0xffffffffu, x, o);
        if ((tid & 31) >= o) x += t;
    }
    if ((tid & 31) == 31) wtot[tid >> 5] = x;
    __syncthreads();
    if (tid < 8) {
        int w = wtot[tid]; int y = w;
        #pragma unroll
        for (int o = 1; o < 8; o <<= 1) {
            int t = __shfl_up_sync(0xffu, y, o);
            if (tid >= o) y += t;
        }
        woff[tid] = y - w;
        if (tid == 7) g_bsums[blockIdx.x] = y;
    }
    __syncthreads();
    if (gi < N_NODES) g_rowptr[gi] = x - v + woff[tid >> 5];
}

__global__ __launch_bounds__(256) void scan2_kernel() {
    __shared__ int wtot[8], woff[8];
    int tid = threadIdx.x;
    int v = (tid < NB_SCAN) ? g_bsums[tid] : 0;
    int x = v;
    #pragma unroll
    for (int o = 1; o < 32; o <<= 1) {
        int t = __shfl_up_sync(0xffffffffu, x, o);
        if ((tid & 31) >= o) x += t;
    }
    if ((tid & 31) == 31) wtot[tid >> 5] = x;
    __syncthreads();
    if (tid < 8) {
        int w = wtot[tid]; int y = w;
        #pragma unroll
        for (int o = 1; o < 8; o <<= 1) {
            int t = __shfl_up_sync(0xffu, y, o);
            if (tid >= o) y += t;
        }
        woff[tid] = y - w;
    }
    __syncthreads();
    if (tid < NB_SCAN) g_bsums[tid] = x - v + woff[tid >> 5];
    if (tid == 255) g_rowptr[N_NODES] = x + woff[7];
}

__global__ void scan3_kernel() {
    int gi = blockIdx.x * blockDim.x + threadIdx.x;
    if (gi < N_NODES) g_rowptr[gi] += g_bsums[blockIdx.x];
}

__global__ void scatter_kernel(const void* ei) {
    int e = blockIdx.x * blockDim.x + threadIdx.x;
    if (e < N_EDGES) {
        int d = ld_idx(ei, (long long)N_EDGES + e);
        int s = ld_idx(ei, e);
        g_colsrc[g_rowptr[d] + atomicAdd(&g_fill[d], 1)] = s;
    }
}

// ---------------- gemm core: CTA 64m x NTn, 4 warps; optional h->smem park ----------------
// mode 1 skip source: fp32 (skip) or fp16 (skip16) — exactly one non-null.
template<int NT>
__device__ __forceinline__ void gemm_core(char* sm,
    const __half* __restrict__ A16, const __half* __restrict__ btile,
    const float* __restrict__ bias,
    float* C32, int c32s, __half* C16, int c16s,
    int mode, const float* skip, const __half* skip16,
    const float* gate, int m0, int park_h) {
    constexpr int NB2 = NT / 32;
    constexpr uint32_t BOFF = 64 * 272;
    uint32_t sbase = smem_u32(sm);
    int tid = threadIdx.x, wid = tid >> 5, lane = tid & 31;

    const __half* asrc = A16 + (size_t)m0 * 128;
    #pragma unroll
    for (int i = tid; i < 1024; i += 128) {
        int row = i >> 4, kc = i & 15;
        cp_async16(sbase + row * 272 + kc * 16, asrc + row * 128 + kc * 8);
    }
    #pragma unroll
    for (int i = tid; i < NT * 16; i += 128) {
        int row = i >> 4, kc = i & 15;
        cp_async16(sbase + BOFF + row * 272 + kc * 16, btile + row * 128 + kc * 8);
    }
    cp_async_wait_all();
    __syncthreads();

    int wm = wid & 1, wn = wid >> 1;
    uint32_t arowoff[2];
    #pragma unroll
    for (int mb = 0; mb < 2; ++mb) {
        int arow = wm * 32 + mb * 16 + (lane & 15);
        arowoff[mb] = (uint32_t)arow * 272u + (uint32_t)(lane & 16);
    }
    uint32_t browoff[NB2];
    #pragma unroll
    for (int nb2 = 0; nb2 < NB2; ++nb2) {
        int brow = wn * (NT / 2) + nb2 * 16 + (lane & 7) + ((lane & 16) >> 1);
        browoff[nb2] = (uint32_t)brow * 272u + (uint32_t)((lane & 8) << 1);
    }

    float acc[2][2 * NB2][4];
    #pragma unroll
    for (int mb = 0; mb < 2; ++mb)
        #pragma unroll
        for (int nb = 0; nb < 2 * NB2; ++nb)
            #pragma unroll
            for (int j = 0; j < 4; ++j) acc[mb][nb][j] = 0.0f;

    #pragma unroll
    for (int ks = 0; ks < 8; ++ks) {
        uint32_t kb = (uint32_t)ks * 32u;
        uint32_t a[2][4];
        ldsm4(a[0], sbase + arowoff[0] + kb);
        ldsm4(a[1], sbase + arowoff[1] + kb);
        #pragma unroll
        for (int nb2 = 0; nb2 < NB2; ++nb2) {
            uint32_t bb[4];
            ldsm4(bb, sbase + BOFF + browoff[nb2] + kb);
            mma16816(acc[0][2 * nb2],     a[0], bb[0], bb[1]);
            mma16816(acc[1][2 * nb2],     a[1], bb[0], bb[1]);
            mma16816(acc[0][2 * nb2 + 1], a[0], bb[2], bb[3]);
            mma16816(acc[1][2 * nb2 + 1], a[1], bb[2], bb[3]);
        }
    }

    if (park_h) __syncthreads();

    float beta = 0.f, ombeta = 0.f;
    if (mode == 1) {
        float g = gate[0];
        beta = 1.f / (1.f + expf(-g));
        ombeta = 1.f - beta;
    }
    int quad = lane >> 2, qt = lane & 3;
    int n0 = wn * (NT / 2);
    #pragma unroll
    for (int mb = 0; mb < 2; ++mb)
        #pragma unroll
        for (int half = 0; half < 2; ++half) {
            int lr = wm * 32 + mb * 16 + quad + half * 8;
            int grow = m0 + lr;
            #pragma unroll
            for (int nb = 0; nb < 2 * NB2; ++nb) {
                int col = n0 + nb * 8 + qt * 2;
                float v0 = acc[mb][nb][2 * half + 0] + bias[col + 0];
                float v1 = acc[mb][nb][2 * half + 1] + bias[col + 1];
                if (mode == 1) {
                    float sx, sy;
                    if (skip) {
                        float2 sv = *(const float2*)(skip + (size_t)grow * 128 + col);
                        sx = sv.x; sy = sv.y;
                    } else {
                        __half2 sh = *(const __half2*)(skip16 + (size_t)grow * 128 + col);
                        sx = __low2float(sh); sy = __high2float(sh);
                    }
                    v0 = fmaxf(beta * v0 + ombeta * sx, 0.f);
                    v1 = fmaxf(beta * v1 + ombeta * sy, 0.f);
                }
                if (C32) {
                    float2 o; o.x = v0; o.y = v1;
                    *(float2*)(C32 + (size_t)grow * c32s + col) = o;
                }
                if (C16)
                    *(__half2*)(C16 + (size_t)grow * c16s + col) = __floats2half2_rn(v0, v1);
                if (park_h)
                    *(__half2*)(sm + lr * 272 + col * 2) = __floats2half2_rn(v0, v1);
            }
        }
}

// ---------------- GEMM kernels ----------------
__global__ __launch_bounds__(128, 4)
void qkv_kernel(int l) {
    extern __shared__ char sm[];
    int bx = blockIdx.x;
    gemm_core<128>(sm, g_a16, g_bt + (size_t)(l * 4 + bx) * 16384,
                   g_bqkv + l * NQKV + bx * 128,
                   nullptr, 0, g_qkv16 + bx * 128, NQKV,
                   0, nullptr, nullptr, nullptr, blockIdx.y * 64, 0);
}

// aw layer 0: h1 written ONLY as fp16 into g_a16 (A input + skip source for layer 1)
__global__ __launch_bounds__(128, 4)
void aw_kernel(const float* __restrict__ ab,
               const float* __restrict__ skipsrc, const float* __restrict__ gate) {
    extern __shared__ char sm[];
    gemm_core<128>(sm, g_agg16, g_bt + (size_t)3 * 16384, ab,
                   nullptr, 0, g_a16, CCH,
                   1, skipsrc, nullptr, gate, blockIdx.y * 64, 0);
}

// aw layer-1 with fused fc: skip read fp16 from g_a16 (== h1); h parked in smem, then fc
#define FC_OFF 52224
__global__ __launch_bounds__(128, 3)
void aw_fc_kernel(const float* __restrict__ ab, const float* __restrict__ gate,
                  const float* __restrict__ fcb, float* __restrict__ out) {
    extern __shared__ char sm[];
    uint32_t sbase = smem_u32(sm);
    int tid = threadIdx.x, wid = tid >> 5, lane = tid & 31;
    int m0 = blockIdx.y * 64;

    {
        const __half* fsrc = g_bt + (size_t)8 * 16384;
        #pragma unroll
        for (int i = tid; i < 1024; i += 128) {
            int row = i >> 4, kc = i & 15;
            cp_async16(sbase + FC_OFF + row * 272 + kc * 16, fsrc + row * 128 + kc * 8);
        }
    }
    gemm_core<128>(sm, g_agg16, g_bt + (size_t)7 * 16384, ab,
                   nullptr, 0, nullptr, 0, 1, nullptr, g_a16, gate, m0, 1);
    __syncthreads();

    int wm = wid & 1, wn = wid >> 1;
    uint32_t arowoff[2];
    #pragma unroll
    for (int mb = 0; mb < 2; ++mb) {
        int arow = wm * 32 + mb * 16 + (lane & 15);
        arowoff[mb] = (uint32_t)arow * 272u + (uint32_t)(lane & 16);
    }
    uint32_t browoff[2];
    #pragma unroll
    for (int nb2 = 0; nb2 < 2; ++nb2) {
        int brow = wn * 32 + nb2 * 16 + (lane & 7) + ((lane & 16) >> 1);
        browoff[nb2] = (uint32_t)brow * 272u + (uint32_t)((lane & 8) << 1);
    }
    float acc[2][4][4];
    #pragma unroll
    for (int mb = 0; mb < 2; ++mb)
        #pragma unroll
        for (int nb = 0; nb < 4; ++nb)
            #pragma unroll
            for (int j = 0; j < 4; ++j) acc[mb][nb][j] = 0.0f;
    #pragma unroll
    for (int ks = 0; ks < 8; ++ks) {
        uint32_t kb = (uint32_t)ks * 32u;
        uint32_t a[2][4];
        ldsm4(a[0], sbase + arowoff[0] + kb);
        ldsm4(a[1], sbase + arowoff[1] + kb);
        #pragma unroll
        for (int nb2 = 0; nb2 < 2; ++nb2) {
            uint32_t bb[4];
            ldsm4(bb, sbase + FC_OFF + browoff[nb2] + kb);
            mma16816(acc[0][2 * nb2],     a[0], bb[0], bb[1]);
            mma16816(acc[1][2 * nb2],     a[1], bb[0], bb[1]);
            mma16816(acc[0][2 * nb2 + 1], a[0], bb[2], bb[3]);
            mma16816(acc[1][2 * nb2 + 1], a[1], bb[2], bb[3]);
        }
    }
    int quad = lane >> 2, qt = lane & 3;
    int n0 = wn * 32;
    #pragma unroll
    for (int mb = 0; mb < 2; ++mb)
        #pragma unroll
        for (int half = 0; half < 2; ++half) {
            int grow = m0 + wm * 32 + mb * 16 + quad + half * 8;
            #pragma unroll
            for (int nb = 0; nb < 4; ++nb) {
                int col = n0 + nb * 8 + qt * 2;
                float2 o;
                o.x = acc[mb][nb][2 * half + 0] + fcb[col + 0];
                o.y = acc[mb][nb][2 * half + 1] + fcb[col + 1];
                *(float2*)(out + (size_t)grow * 64 + col) = o;
            }
        }
}

// ---------------- edge kernel: 2 edges/warp-iter, 16 lanes/edge, 4x pipelined ----------------
__global__ __launch_bounds__(256)
void edge_kernel() {
    int tid = threadIdx.x, wid = tid >> 5, lane = tid & 31;
    int node = blockIdx.x * 8 + wid;      // 5000 x 8 = 40000 exact
    int sub = lane >> 4, j = lane & 15;

    float q[8];
    {
        uint4 qraw = *(const uint4*)(g_qkv16 + (size_t)node * NQKV + 8 * j);
        const __half2* qh = (const __half2*)&qraw;
        #pragma unroll
        for (int t = 0; t < 4; ++t) {
            q[2 * t]     = __low2float(qh[t]);
            q[2 * t + 1] = __high2float(qh[t]);
        }
    }
    int p0 = g_rowptr[node], p1 = g_rowptr[node + 1];
    float s = 0.f;
    float acc[8];
    #pragma unroll
    for (int t = 0; t < 8; ++t) acc[t] = 0.f;

    int iters = (p1 - p0 + 1) >> 1;       // pair slots
    for (int it = 0; it < iters; it += 4) {
        uint4 kr[4], vr[4];
        bool vv[4];
        #pragma unroll
        for (int u = 0; u < 4; ++u) {
            int p = p0 + 2 * (it + u) + sub;
            bool valid = p < p1;
            vv[u] = valid;
            int sn = g_colsrc[valid ? p : p0];
            const __half* base = g_qkv16 + (size_t)sn * NQKV;
            kr[u] = *(const uint4*)(base + CCH + 8 * j);
            vr[u] = *(const uint4*)(base + 2 * CCH + 8 * j);
        }
        #pragma unroll
        for (int u = 0; u < 4; ++u) {
            const __half2* kh = (const __half2*)&kr[u];
            const __half2* vh = (const __half2*)&vr[u];
            float d = 0.f;
            #pragma unroll
            for (int t = 0; t < 4; ++t)
                d += q[2 * t] * __low2float(kh[t]) + q[2 * t + 1] * __high2float(kh[t]);
            d += __shfl_xor_sync(0xffffffffu, d, 1);
            float e = vv[u] ? __expf(d) : 0.f;
            s += e;
            #pragma unroll
            for (int t = 0; t < 4; ++t) {
                acc[2 * t]     = fmaf(e, __low2float(vh[t]), acc[2 * t]);
                acc[2 * t + 1] = fmaf(e, __high2float(vh[t]), acc[2 * t + 1]);
            }
        }
    }

    s += __shfl_xor_sync(0xffffffffu, s, 16);
    #pragma unroll
    for (int t = 0; t < 8; ++t)
        acc[t] += __shfl_xor_sync(0xffffffffu, acc[t], 16);

    if (sub == 0) {
        float inv = 1.f / (s + 1e-16f);
        __half2 o[4];
        #pragma unroll
        for (int t = 0; t < 4; ++t)
            o[t] = __floats2half2_rn(gelu_tanh(acc[2 * t] * inv),
                                     gelu_tanh(acc[2 * t + 1] * inv));
        *(uint4*)(g_agg16 + (size_t)node * CCH + 8 * j) = *(uint4*)o;
    }
}

// ---------------- host launch ----------------
#define SMEM_G128 (64 * 272 + 128 * 272)       // 52224
#define SMEM_AWFC (52224 + 64 * 272)           // 69632

extern "C" void kernel_launch(void* const* d_in, const int* in_sizes, int n_in,
                              void* d_out, int out_size) {
    const float* x    = (const float*)d_in[0];
    const void*  ei   = d_in[1];
    const float* Wk   = (const float*)d_in[2];
    const float* bk   = (const float*)d_in[3];
    const float* Wq   = (const float*)d_in[4];
    const float* bq   = (const float*)d_in[5];
    const float* Wv   = (const float*)d_in[6];
    const float* bv   = (const float*)d_in[7];
    const float* a_rel = (const float*)d_in[8];
    const float* m_rel = (const float*)d_in[9];
    const float* p_rel = (const float*)d_in[10];
    const float* skip  = (const float*)d_in[11];
    const float* aW    = (const float*)d_in[12];
    const float* ab    = (const float*)d_in[13];
    const float* fcW   = (const float*)d_in[14];
    const float* fcb   = (const float*)d_in[15];
    float* out = (float*)d_out;

    cudaFuncSetAttribute(qkv_kernel,   cudaFuncAttributeMaxDynamicSharedMemorySize, SMEM_G128);
    cudaFuncSetAttribute(aw_kernel,    cudaFuncAttributeMaxDynamicSharedMemorySize, SMEM_G128);
    cudaFuncSetAttribute(aw_fc_kernel, cudaFuncAttributeMaxDynamicSharedMemorySize, SMEM_AWFC);

    // #1 mega_prep, #2 hist, #3 scan1, #4 QKV layer 0 (ncu slot)
    mega_prep<<<MEGA_BLKS, 256>>>(x, ei, Wk, bk, Wq, bq, Wv, bv,
                                  a_rel, m_rel, p_rel, aW, fcW);
    hist_kernel<<<(N_EDGES + 255) / 256, 256>>>(ei);
    scan1_kernel<<<NB_SCAN, 256>>>();

    qkv_kernel<<<dim3(3, 625), 128, SMEM_G128>>>(0);

    scan2_kernel<<<1, 256>>>();
    scan3_kernel<<<NB_SCAN, 256>>>();
    scatter_kernel<<<(N_EDGES + 255) / 256, 256>>>(ei);

    edge_kernel<<<5000, 256>>>();
    aw_kernel<<<dim3(1, 625), 128, SMEM_G128>>>(ab, x, skip);

    qkv_kernel<<<dim3(3, 625), 128, SMEM_G128>>>(1);
    edge_kernel<<<5000, 256>>>();
    aw_fc_kernel<<<dim3(1, 625), 128, SMEM_AWFC>>>(ab + CCH, skip + 1, fcb, out);
}

// round 14
// speedup vs baseline: 1.1684x; 1.0735x over previous
#include <cuda_runtime.h>
#include <cuda_fp16.h>
#include <math.h>
#include <stdint.h>

#define N_NODES 40000
#define N_PAD   40064
#define N_EDGES 640000
#define CCH 128
#define NQKV 384
#define NB_SCAN 157

// prep_main block ranges
#define BIASB  3
#define CVTB   10016           // N_PAD*64 / 256 exact
#define PREPB  544             // 139264 / 256
#define PMAIN_BLKS (BIASB + CVTB + PREPB)

// ---------------- device scratch ----------------
__device__ __half g_a16[(size_t)N_PAD * CCH];       // layer A input; holds h1 (fp16) after aw0
__device__ __half g_qkv16[(size_t)N_PAD * NQKV];
__device__ __half g_agg16[(size_t)N_PAD * CCH];
__device__ int    g_rowptr[N_NODES + 1];
__device__ int    g_colsrc[N_EDGES];
__device__ int    g_counts[N_NODES];
__device__ int    g_fill[N_NODES];
__device__ int    g_bsums[256];
__device__ float  g_bqkv[2 * NQKV];
__device__ __half g_bt[139264];
__device__ int    g_use64;

// ---------------- helpers ----------------
__device__ __forceinline__ uint32_t smem_u32(const void* p) {
    uint32_t a;
    asm("{ .reg .u64 t; cvta.to.shared.u64 t, %1; cvt.u32.u64 %0, t; }" : "=r"(a) : "l"(p));
    return a;
}
__device__ __forceinline__ void cp_async16(uint32_t dst, const void* src) {
    asm volatile("cp.async.ca.shared.global [%0], [%1], 16;" :: "r"(dst), "l"(src));
}
__device__ __forceinline__ void cp_async_wait_all() {
    asm volatile("cp.async.commit_group;");
    asm volatile("cp.async.wait_group 0;");
}
__device__ __forceinline__ int ld_idx(const void* ei, long long pos) {
    if (g_use64) return (int)((const long long*)ei)[pos];
    return ((const int*)ei)[pos];
}
__device__ __forceinline__ float gelu_tanh(float x) {
    float x3 = x * x * x;
    return 0.5f * x * (1.0f + tanhf(0.7978845608028654f * (x + 0.044715f * x3)));
}
__device__ __forceinline__ void ldsm4(uint32_t* r, uint32_t addr) {
    asm volatile("ldmatrix.sync.aligned.m8n8.x4.shared.b16 {%0,%1,%2,%3}, [%4];"
        : "=r"(r[0]), "=r"(r[1]), "=r"(r[2]), "=r"(r[3]) : "r"(addr));
}
__device__ __forceinline__ void mma16816(float* c, const uint32_t* a, uint32_t b0, uint32_t b1) {
    asm volatile("mma.sync.aligned.m16n8k16.row.col.f32.f16.f16.f32 "
        "{%0,%1,%2,%3}, {%4,%5,%6,%7}, {%8,%9}, {%0,%1,%2,%3};"
        : "+f"(c[0]), "+f"(c[1]), "+f"(c[2]), "+f"(c[3])
        : "r"(a[0]), "r"(a[1]), "r"(a[2]), "r"(a[3]), "r"(b0), "r"(b1));
}

// ---------------- prep_main: bias | cvt_x | prep_b(direct) ----------------
__global__ __launch_bounds__(256)
void prep_main(const float* __restrict__ x,
               const float* Wk, const float* bk, const float* Wq, const float* bq,
               const float* Wv, const float* bv,
               const float* a_rel, const float* m_rel, const float* p_rel,
               const float* aW, const float* fcW) {
    int b = blockIdx.x, tid = threadIdx.x;
    if (b < BIASB) {
        int idx = b * 256 + tid;
        if (idx < 768) {
            int l = idx / NQKV, c = idx % NQKV;
            int t = c >> 7, cc = c & 127, h = cc >> 4, eo = cc & 15;
            float bias;
            if (t == 0) bias = bq[l * 128 + cc] * p_rel[l * 8 + h] * 0.25f;
            else {
                const float* bm = (t == 1) ? bk : bv;
                const float* R  = (t == 1) ? a_rel : m_rel;
                float sb = 0.f;
                #pragma unroll
                for (int d = 0; d < 16; ++d)
                    sb += bm[l * 128 + h * 16 + d] * R[((l * 8 + h) * 16 + d) * 16 + eo];
                bias = sb;
            }
            g_bqkv[l * NQKV + c] = bias;
        }
        return;
    }
    b -= BIASB;
    if (b < CVTB) {
        int i = b * 256 + tid;
        if (i < N_NODES * 64) {
            float2 v = ((const float2*)x)[i];
            ((__half2*)g_a16)[i] = __floats2half2_rn(v.x, v.y);
        } else {
            ((__half2*)g_a16)[i] = __floats2half2_rn(0.f, 0.f);
        }
        return;
    }
    b -= CVTB;
    {
        int e = b * 256 + tid;
        float val;
        if (e < 131072) {
            int tile = e >> 14, within = e & 16383;
            int nn = within >> 7, k = within & 127;
            int l = tile >> 2, t = tile & 3;
            if (t == 0)      val = Wq[(size_t)l * 16384 + k * 128 + nn] * p_rel[l * 8 + (nn >> 4)] * 0.25f;
            else if (t == 3) val = aW[(size_t)l * 16384 + k * 128 + nn];
            else {
                const float* Wm = (t == 1) ? Wk : Wv;
                const float* R  = (t == 1) ? a_rel : m_rel;
                int h = nn >> 4, eo = nn & 15;
                float s = 0.f;
                #pragma unroll
                for (int d = 0; d < 16; ++d)
                    s += Wm[(size_t)l * 16384 + k * 128 + h * 16 + d] * R[((l * 8 + h) * 16 + d) * 16 + eo];
                val = s;
            }
        } else {
            int e2 = e - 131072;
            int nn = e2 >> 7, k = e2 & 127;
            val = fcW[k * 64 + nn];
        }
        g_bt[e] = __float2half(val);
    }
}

// ---------------- CSR build (stream B) ----------------
__global__ void init_kernel(const int* ei_words) {
    int gi = blockIdx.x * blockDim.x + threadIdx.x;
    if (gi < N_NODES) { g_counts[gi] = 0; g_fill[gi] = 0; }
    if (blockIdx.x == 0) {
        __shared__ int any;
        if (threadIdx.x == 0) any = 0;
        __syncthreads();
        int v = 0;
        for (int i = threadIdx.x; i < 2048; i += 256) v |= ei_words[2 * i + 1];
        if (v) atomicOr(&any, 1);
        __syncthreads();
        if (threadIdx.x == 0) g_use64 = (any == 0) ? 1 : 0;
    }
}

__global__ void hist_kernel(const void* ei) {
    int e = blockIdx.x * blockDim.x + threadIdx.x;
    if (e < N_EDGES) atomicAdd(&g_counts[ld_idx(ei, (long long)N_EDGES + e)], 1);
}

__global__ __launch_bounds__(256) void scan1_kernel() {
    __shared__ int wtot[8], woff[8];
    int tid = threadIdx.x;
    int gi = blockIdx.x * 256 + tid;
    int v = (gi < N_NODES) ? g_counts[gi] : 0;
    int x = v;
    #pragma unroll
    for (int o = 1; o < 32; o <<= 1) {
        int t = __shfl_up_sync(0xffffffffu, x, o);
        if ((tid & 31) >= o) x += t;
    }
    if ((tid & 31) == 31) wtot[tid >> 5] = x;
    __syncthreads();
    if (tid < 8) {
        int w = wtot[tid]; int y = w;
        #pragma unroll
        for (int o = 1; o < 8; o <<= 1) {
            int t = __shfl_up_sync(0xffu, y, o);
            if (tid >= o) y += t;
        }
        woff[tid] = y - w;
        if (tid == 7) g_bsums[blockIdx.x] = y;
    }
    __syncthreads();
    if (gi < N_NODES) g_rowptr[gi] = x - v + woff[tid >> 5];
}

__global__ __launch_bounds__(256) void scan2_kernel() {
    __shared__ int wtot[8], woff[8];
    int tid = threadIdx.x;
    int v = (tid < NB_SCAN) ? g_bsums[tid] : 0;
    int x = v;
    #pragma unroll
    for (int o = 1; o < 32; o <<= 1) {
        int t = __shfl_up_sync(0xffffffffu, x, o);
        if ((tid & 31) >= o) x += t;
    }
    if ((tid & 31) == 31) wtot[tid >> 5] = x;
    __syncthreads();
    if (tid < 8) {
        int w = wtot[tid]; int y = w;
        #pragma unroll
        for (int o = 1; o < 8; o <<= 1) {
            int t = __shfl_up_sync(0xffu, y, o);
            if (tid >= o) y += t;
        }
        woff[tid] = y - w;
    }
    __syncthreads();
    if (tid < NB_SCAN) g_bsums[tid] = x - v + woff[tid >> 5];
    if (tid == 255) g_rowptr[N_NODES] = x + woff[7];
}

__global__ void scan3_kernel() {
    int gi = blockIdx.x * blockDim.x + threadIdx.x;
    if (gi < N_NODES) g_rowptr[gi] += g_bsums[blockIdx.x];
}

__global__ void scatter_kernel(const void* ei) {
    int e = blockIdx.x * blockDim.x + threadIdx.x;
    if (e < N_EDGES) {
        int d = ld_idx(ei, (long long)N_EDGES + e);
        int s = ld_idx(ei, e);
        g_colsrc[g_rowptr[d] + atomicAdd(&g_fill[d], 1)] = s;
    }
}

// ---------------- gemm core: CTA 64m x NTn, 4 warps; optional h->smem park ----------------
template<int NT>
__device__ __forceinline__ void gemm_core(char* sm,
    const __half* __restrict__ A16, const __half* __restrict__ btile,
    const float* __restrict__ bias,
    float* C32, int c32s, __half* C16, int c16s,
    int mode, const float* skip, const __half* skip16,
    const float* gate, int m0, int park_h) {
    constexpr int NB2 = NT / 32;
    constexpr uint32_t BOFF = 64 * 272;
    uint32_t sbase = smem_u32(sm);
    int tid = threadIdx.x, wid = tid >> 5, lane = tid & 31;

    const __half* asrc = A16 + (size_t)m0 * 128;
    #pragma unroll
    for (int i = tid; i < 1024; i += 128) {
        int row = i >> 4, kc = i & 15;
        cp_async16(sbase + row * 272 + kc * 16, asrc + row * 128 + kc * 8);
    }
    #pragma unroll
    for (int i = tid; i < NT * 16; i += 128) {
        int row = i >> 4, kc = i & 15;
        cp_async16(sbase + BOFF + row * 272 + kc * 16, btile + row * 128 + kc * 8);
    }
    cp_async_wait_all();
    __syncthreads();

    int wm = wid & 1, wn = wid >> 1;
    uint32_t arowoff[2];
    #pragma unroll
    for (int mb = 0; mb < 2; ++mb) {
        int arow = wm * 32 + mb * 16 + (lane & 15);
        arowoff[mb] = (uint32_t)arow * 272u + (uint32_t)(lane & 16);
    }
    uint32_t browoff[NB2];
    #pragma unroll
    for (int nb2 = 0; nb2 < NB2; ++nb2) {
        int brow = wn * (NT / 2) + nb2 * 16 + (lane & 7) + ((lane & 16) >> 1);
        browoff[nb2] = (uint32_t)brow * 272u + (uint32_t)((lane & 8) << 1);
    }

    float acc[2][2 * NB2][4];
    #pragma unroll
    for (int mb = 0; mb < 2; ++mb)
        #pragma unroll
        for (int nb = 0; nb < 2 * NB2; ++nb)
            #pragma unroll
            for (int j = 0; j < 4; ++j) acc[mb][nb][j] = 0.0f;

    #pragma unroll
    for (int ks = 0; ks < 8; ++ks) {
        uint32_t kb = (uint32_t)ks * 32u;
        uint32_t a[2][4];
        ldsm4(a[0], sbase + arowoff[0] + kb);
        ldsm4(a[1], sbase + arowoff[1] + kb);
        #pragma unroll
        for (int nb2 = 0; nb2 < NB2; ++nb2) {
            uint32_t bb[4];
            ldsm4(bb, sbase + BOFF + browoff[nb2] + kb);
            mma16816(acc[0][2 * nb2],     a[0], bb[0], bb[1]);
            mma16816(acc[1][2 * nb2],     a[1], bb[0], bb[1]);
            mma16816(acc[0][2 * nb2 + 1], a[0], bb[2], bb[3]);
            mma16816(acc[1][2 * nb2 + 1], a[1], bb[2], bb[3]);
        }
    }

    if (park_h) __syncthreads();

    float beta = 0.f, ombeta = 0.f;
    if (mode == 1) {
        float g = gate[0];
        beta = 1.f / (1.f + expf(-g));
        ombeta = 1.f - beta;
    }
    int quad = lane >> 2, qt = lane & 3;
    int n0 = wn * (NT / 2);
    #pragma unroll
    for (int mb = 0; mb < 2; ++mb)
        #pragma unroll
        for (int half = 0; half < 2; ++half) {
            int lr = wm * 32 + mb * 16 + quad + half * 8;
            int grow = m0 + lr;
            #pragma unroll
            for (int nb = 0; nb < 2 * NB2; ++nb) {
                int col = n0 + nb * 8 + qt * 2;
                float v0 = acc[mb][nb][2 * half + 0] + bias[col + 0];
                float v1 = acc[mb][nb][2 * half + 1] + bias[col + 1];
                if (mode == 1) {
                    float sx, sy;
                    if (skip) {
                        float2 sv = *(const float2*)(skip + (size_t)grow * 128 + col);
                        sx = sv.x; sy = sv.y;
                    } else {
                        __half2 sh = *(const __half2*)(skip16 + (size_t)grow * 128 + col);
                        sx = __low2float(sh); sy = __high2float(sh);
                    }
                    v0 = fmaxf(beta * v0 + ombeta * sx, 0.f);
                    v1 = fmaxf(beta * v1 + ombeta * sy, 0.f);
                }
                if (C32) {
                    float2 o; o.x = v0; o.y = v1;
                    *(float2*)(C32 + (size_t)grow * c32s + col) = o;
                }
                if (C16)
                    *(__half2*)(C16 + (size_t)grow * c16s + col) = __floats2half2_rn(v0, v1);
                if (park_h)
                    *(__half2*)(sm + lr * 272 + col * 2) = __floats2half2_rn(v0, v1);
            }
        }
}

// ---------------- GEMM kernels ----------------
__global__ __launch_bounds__(128, 4)
void qkv_kernel(int l) {
    extern __shared__ char sm[];
    int bx = blockIdx.x;
    gemm_core<128>(sm, g_a16, g_bt + (size_t)(l * 4 + bx) * 16384,
                   g_bqkv + l * NQKV + bx * 128,
                   nullptr, 0, g_qkv16 + bx * 128, NQKV,
                   0, nullptr, nullptr, nullptr, blockIdx.y * 64, 0);
}

// aw layer 0: h1 written ONLY as fp16 into g_a16
__global__ __launch_bounds__(128, 4)
void aw_kernel(const float* __restrict__ ab,
               const float* __restrict__ skipsrc, const float* __restrict__ gate) {
    extern __shared__ char sm[];
    gemm_core<128>(sm, g_agg16, g_bt + (size_t)3 * 16384, ab,
                   nullptr, 0, g_a16, CCH,
                   1, skipsrc, nullptr, gate, blockIdx.y * 64, 0);
}

// aw layer-1 with fused fc: skip read fp16 from g_a16 (== h1)
#define FC_OFF 52224
__global__ __launch_bounds__(128, 3)
void aw_fc_kernel(const float* __restrict__ ab, const float* __restrict__ gate,
                  const float* __restrict__ fcb, float* __restrict__ out) {
    extern __shared__ char sm[];
    uint32_t sbase = smem_u32(sm);
    int tid = threadIdx.x, wid = tid >> 5, lane = tid & 31;
    int m0 = blockIdx.y * 64;

    {
        const __half* fsrc = g_bt + (size_t)8 * 16384;
        #pragma unroll
        for (int i = tid; i < 1024; i += 128) {
            int row = i >> 4, kc = i & 15;
            cp_async16(sbase + FC_OFF + row * 272 + kc * 16, fsrc + row * 128 + kc * 8);
        }
    }
    gemm_core<128>(sm, g_agg16, g_bt + (size_t)7 * 16384, ab,
                   nullptr, 0, nullptr, 0, 1, nullptr, g_a16, gate, m0, 1);
    __syncthreads();

    int wm = wid & 1, wn = wid >> 1;
    uint32_t arowoff[2];
    #pragma unroll
    for (int mb = 0; mb < 2; ++mb) {
        int arow = wm * 32 + mb * 16 + (lane & 15);
        arowoff[mb] = (uint32_t)arow * 272u + (uint32_t)(lane & 16);
    }
    uint32_t browoff[2];
    #pragma unroll
    for (int nb2 = 0; nb2 < 2; ++nb2) {
        int brow = wn * 32 + nb2 * 16 + (lane & 7) + ((lane & 16) >> 1);
        browoff[nb2] = (uint32_t)brow * 272u + (uint32_t)((lane & 8) << 1);
    }
    float acc[2][4][4];
    #pragma unroll
    for (int mb = 0; mb < 2; ++mb)
        #pragma unroll
        for (int nb = 0; nb < 4; ++nb)
            #pragma unroll
            for (int j = 0; j < 4; ++j) acc[mb][nb][j] = 0.0f;
    #pragma unroll
    for (int ks = 0; ks < 8; ++ks) {
        uint32_t kb = (uint32_t)ks * 32u;
        uint32_t a[2][4];
        ldsm4(a[0], sbase + arowoff[0] + kb);
        ldsm4(a[1], sbase + arowoff[1] + kb);
        #pragma unroll
        for (int nb2 = 0; nb2 < 2; ++nb2) {
            uint32_t bb[4];
            ldsm4(bb, sbase + FC_OFF + browoff[nb2] + kb);
            mma16816(acc[0][2 * nb2],     a[0], bb[0], bb[1]);
            mma16816(acc[1][2 * nb2],     a[1], bb[0], bb[1]);
            mma16816(acc[0][2 * nb2 + 1], a[0], bb[2], bb[3]);
            mma16816(acc[1][2 * nb2 + 1], a[1], bb[2], bb[3]);
        }
    }
    int quad = lane >> 2, qt = lane & 3;
    int n0 = wn * 32;
    #pragma unroll
    for (int mb = 0; mb < 2; ++mb)
        #pragma unroll
        for (int half = 0; half < 2; ++half) {
            int grow = m0 + wm * 32 + mb * 16 + quad + half * 8;
            #pragma unroll
            for (int nb = 0; nb < 4; ++nb) {
                int col = n0 + nb * 8 + qt * 2;
                float2 o;
                o.x = acc[mb][nb][2 * half + 0] + fcb[col + 0];
                o.y = acc[mb][nb][2 * half + 1] + fcb[col + 1];
                *(float2*)(out + (size_t)grow * 64 + col) = o;
            }
        }
}

// ---------------- edge kernel: 2 edges/warp-iter, 16 lanes/edge, 2x pipelined ----------------
__global__ __launch_bounds__(256)
void edge_kernel() {
    int tid = threadIdx.x, wid = tid >> 5, lane = tid & 31;
    int node = blockIdx.x * 8 + wid;
    int sub = lane >> 4, j = lane & 15;

    float q[8];
    {
        uint4 qraw = *(const uint4*)(g_qkv16 + (size_t)node * NQKV + 8 * j);
        const __half2* qh = (const __half2*)&qraw;
        #pragma unroll
        for (int t = 0; t < 4; ++t) {
            q[2 * t]     = __low2float(qh[t]);
            q[2 * t + 1] = __high2float(qh[t]);
        }
    }
    int p0 = g_rowptr[node], p1 = g_rowptr[node + 1];
    float s = 0.f;
    float acc[8];
    #pragma unroll
    for (int t = 0; t < 8; ++t) acc[t] = 0.f;

    int iters = (p1 - p0 + 1) >> 1;
    for (int it = 0; it < iters; it += 2) {
        int pA = p0 + 2 * it + sub;
        int pB = pA + 2;
        bool vA = pA < p1;
        bool vB = (it + 1 < iters) && (pB < p1);
        int snA = g_colsrc[vA ? pA : p0];
        int snB = g_colsrc[vB ? pB : p0];
        const __half* baseA = g_qkv16 + (size_t)snA * NQKV;
        const __half* baseB = g_qkv16 + (size_t)snB * NQKV;
        uint4 kA = *(const uint4*)(baseA + CCH + 8 * j);
        uint4 vA_ = *(const uint4*)(baseA + 2 * CCH + 8 * j);
        uint4 kB = *(const uint4*)(baseB + CCH + 8 * j);
        uint4 vB_ = *(const uint4*)(baseB + 2 * CCH + 8 * j);
        {
            const __half2* kh = (const __half2*)&kA;
            const __half2* vh = (const __half2*)&vA_;
            float d = 0.f;
            #pragma unroll
            for (int t = 0; t < 4; ++t)
                d += q[2 * t] * __low2float(kh[t]) + q[2 * t + 1] * __high2float(kh[t]);
            d += __shfl_xor_sync(0xffffffffu, d, 1);
            float e = vA ? __expf(d) : 0.f;
            s += e;
            #pragma unroll
            for (int t = 0; t < 4; ++t) {
                acc[2 * t]     = fmaf(e, __low2float(vh[t]), acc[2 * t]);
                acc[2 * t + 1] = fmaf(e, __high2float(vh[t]), acc[2 * t + 1]);
            }
        }
        {
            const __half2* kh = (const __half2*)&kB;
            const __half2* vh = (const __half2*)&vB_;
            float d = 0.f;
            #pragma unroll
            for (int t = 0; t < 4; ++t)
                d += q[2 * t] * __low2float(kh[t]) + q[2 * t + 1] * __high2float(kh[t]);
            d += __shfl_xor_sync(0xffffffffu, d, 1);
            float e = vB ? __expf(d) : 0.f;
            s += e;
            #pragma unroll
            for (int t = 0; t < 4; ++t) {
                acc[2 * t]     = fmaf(e, __low2float(vh[t]), acc[2 * t]);
                acc[2 * t + 1] = fmaf(e, __high2float(vh[t]), acc[2 * t + 1]);
            }
        }
    }

    s += __shfl_xor_sync(0xffffffffu, s, 16);
    #pragma unroll
    for (int t = 0; t < 8; ++t)
        acc[t] += __shfl_xor_sync(0xffffffffu, acc[t], 16);

    if (sub == 0) {
        float inv = 1.f / (s + 1e-16f);
        __half2 o[4];
        #pragma unroll
        for (int t = 0; t < 4; ++t)
            o[t] = __floats2half2_rn(gelu_tanh(acc[2 * t] * inv),
                                     gelu_tanh(acc[2 * t + 1] * inv));
        *(uint4*)(g_agg16 + (size_t)node * CCH + 8 * j) = *(uint4*)o;
    }
}

// ---------------- host launch ----------------
#define SMEM_G128 (64 * 272 + 128 * 272)       // 52224
#define SMEM_AWFC (52224 + 64 * 272)           // 69632

extern "C" void kernel_launch(void* const* d_in, const int* in_sizes, int n_in,
                              void* d_out, int out_size) {
    const float* x    = (const float*)d_in[0];
    const void*  ei   = d_in[1];
    const float* Wk   = (const float*)d_in[2];
    const float* bk   = (const float*)d_in[3];
    const float* Wq   = (const float*)d_in[4];
    const float* bq   = (const float*)d_in[5];
    const float* Wv   = (const float*)d_in[6];
    const float* bv   = (const float*)d_in[7];
    const float* a_rel = (const float*)d_in[8];
    const float* m_rel = (const float*)d_in[9];
    const float* p_rel = (const float*)d_in[10];
    const float* skip  = (const float*)d_in[11];
    const float* aW    = (const float*)d_in[12];
    const float* ab    = (const float*)d_in[13];
    const float* fcW   = (const float*)d_in[14];
    const float* fcb   = (const float*)d_in[15];
    float* out = (float*)d_out;

    // One-time side-stream + events (host resources only; created on the first,
    // non-captured correctness call; identical launched work every call).
    static cudaStream_t sB = nullptr;
    static cudaEvent_t eFork = nullptr, eJoin = nullptr;
    if (!sB) {
        cudaStreamCreateWithFlags(&sB, cudaStreamNonBlocking);
        cudaEventCreateWithFlags(&eFork, cudaEventDisableTiming);
        cudaEventCreateWithFlags(&eJoin, cudaEventDisableTiming);
        cudaFuncSetAttribute(qkv_kernel,   cudaFuncAttributeMaxDynamicSharedMemorySize, SMEM_G128);
        cudaFuncSetAttribute(aw_kernel,    cudaFuncAttributeMaxDynamicSharedMemorySize, SMEM_G128);
        cudaFuncSetAttribute(aw_fc_kernel, cudaFuncAttributeMaxDynamicSharedMemorySize, SMEM_AWFC);
    }

    // Fork: CSR chain on stream B, prep+qkv0 on main stream (independent).
    cudaEventRecord(eFork, 0);
    cudaStreamWaitEvent(sB, eFork, 0);

    init_kernel<<<NB_SCAN, 256, 0, sB>>>((const int*)ei);
    hist_kernel<<<(N_EDGES + 255) / 256, 256, 0, sB>>>(ei);
    scan1_kernel<<<NB_SCAN, 256, 0, sB>>>();
    scan2_kernel<<<1, 256, 0, sB>>>();
    scan3_kernel<<<NB_SCAN, 256, 0, sB>>>();
    scatter_kernel<<<(N_EDGES + 255) / 256, 256, 0, sB>>>(ei);
    cudaEventRecord(eJoin, sB);

    prep_main<<<PMAIN_BLKS, 256>>>(x, Wk, bk, Wq, bq, Wv, bv,
                                   a_rel, m_rel, p_rel, aW, fcW);
    qkv_kernel<<<dim3(3, 625), 128, SMEM_G128>>>(0);

    // Join: edge needs both qkv16 (main) and CSR (sB).
    cudaStreamWaitEvent(0, eJoin, 0);

    edge_kernel<<<5000, 256>>>();
    aw_kernel<<<dim3(1, 625), 128, SMEM_G128>>>(ab, x, skip);
    qkv_kernel<<<dim3(3, 625), 128, SMEM_G128>>>(1);
    edge_kernel<<<5000, 256>>>();
    aw_fc_kernel<<<dim3(1, 625), 128, SMEM_AWFC>>>(ab + CCH, skip + 1, fcb, out);
}

// round 16
// speedup vs baseline: 1.1724x; 1.0034x over previous
#include <cuda_runtime.h>
#include <cuda_fp16.h>
#include <math.h>
#include <stdint.h>

#define N_NODES 40000
#define N_PAD   40064
#define N_EDGES 640000
#define CCH 128
#define NQKV 384
#define NB_SCAN 157

// prep_main block ranges
#define BIASB  3
#define CVTB   10016           // N_PAD*64 / 256 exact
#define PREPB  544             // 139264 / 256
#define PMAIN_BLKS (BIASB + CVTB + PREPB)

// ---------------- device scratch ----------------
__device__ __half g_a16[(size_t)N_PAD * CCH];       // x fp16; holds h1 fp16 after aw0 (skip for aw_fc)
__device__ __half g_qkv16[(size_t)N_PAD * NQKV];
__device__ __half g_agg16[(size_t)N_PAD * CCH];
__device__ int    g_rowptr[N_NODES + 1];
__device__ int    g_colsrc[N_EDGES];
__device__ int    g_counts[N_NODES];
__device__ int    g_fill[N_NODES];
__device__ int    g_bsums[256];
__device__ float  g_bqkv[2 * NQKV];
__device__ __half g_bt[139264];
__device__ int    g_use64;

// ---------------- helpers ----------------
__device__ __forceinline__ uint32_t smem_u32(const void* p) {
    uint32_t a;
    asm("{ .reg .u64 t; cvta.to.shared.u64 t, %1; cvt.u32.u64 %0, t; }" : "=r"(a) : "l"(p));
    return a;
}
__device__ __forceinline__ void cp_async16(uint32_t dst, const void* src) {
    asm volatile("cp.async.ca.shared.global [%0], [%1], 16;" :: "r"(dst), "l"(src));
}
__device__ __forceinline__ void cp_async_wait_all() {
    asm volatile("cp.async.commit_group;");
    asm volatile("cp.async.wait_group 0;");
}
__device__ __forceinline__ int ld_idx(const void* ei, long long pos) {
    if (g_use64) return (int)((const long long*)ei)[pos];
    return ((const int*)ei)[pos];
}
__device__ __forceinline__ float gelu_tanh(float x) {
    float x3 = x * x * x;
    return 0.5f * x * (1.0f + tanhf(0.7978845608028654f * (x + 0.044715f * x3)));
}
__device__ __forceinline__ void ldsm4(uint32_t* r, uint32_t addr) {
    asm volatile("ldmatrix.sync.aligned.m8n8.x4.shared.b16 {%0,%1,%2,%3}, [%4];"
        : "=r"(r[0]), "=r"(r[1]), "=r"(r[2]), "=r"(r[3]) : "r"(addr));
}
__device__ __forceinline__ void mma16816(float* c, const uint32_t* a, uint32_t b0, uint32_t b1) {
    asm volatile("mma.sync.aligned.m16n8k16.row.col.f32.f16.f16.f32 "
        "{%0,%1,%2,%3}, {%4,%5,%6,%7}, {%8,%9}, {%0,%1,%2,%3};"
        : "+f"(c[0]), "+f"(c[1]), "+f"(c[2]), "+f"(c[3])
        : "r"(a[0]), "r"(a[1]), "r"(a[2]), "r"(a[3]), "r"(b0), "r"(b1));
}

// ---------------- prep_main: bias | cvt_x | prep_b(direct) ----------------
__global__ __launch_bounds__(256)
void prep_main(const float* __restrict__ x,
               const float* Wk, const float* bk, const float* Wq, const float* bq,
               const float* Wv, const float* bv,
               const float* a_rel, const float* m_rel, const float* p_rel,
               const float* aW, const float* fcW) {
    int b = blockIdx.x, tid = threadIdx.x;
    if (b < BIASB) {
        int idx = b * 256 + tid;
        if (idx < 768) {
            int l = idx / NQKV, c = idx % NQKV;
            int t = c >> 7, cc = c & 127, h = cc >> 4, eo = cc & 15;
            float bias;
            if (t == 0) bias = bq[l * 128 + cc] * p_rel[l * 8 + h] * 0.25f;
            else {
                const float* bm = (t == 1) ? bk : bv;
                const float* R  = (t == 1) ? a_rel : m_rel;
                float sb = 0.f;
                #pragma unroll
                for (int d = 0; d < 16; ++d)
                    sb += bm[l * 128 + h * 16 + d] * R[((l * 8 + h) * 16 + d) * 16 + eo];
                bias = sb;
            }
            g_bqkv[l * NQKV + c] = bias;
        }
        return;
    }
    b -= BIASB;
    if (b < CVTB) {
        int i = b * 256 + tid;
        if (i < N_NODES * 64) {
            float2 v = ((const float2*)x)[i];
            ((__half2*)g_a16)[i] = __floats2half2_rn(v.x, v.y);
        } else {
            ((__half2*)g_a16)[i] = __floats2half2_rn(0.f, 0.f);
        }
        return;
    }
    b -= CVTB;
    {
        int e = b * 256 + tid;
        float val;
        if (e < 131072) {
            int tile = e >> 14, within = e & 16383;
            int nn = within >> 7, k = within & 127;
            int l = tile >> 2, t = tile & 3;
            if (t == 0)      val = Wq[(size_t)l * 16384 + k * 128 + nn] * p_rel[l * 8 + (nn >> 4)] * 0.25f;
            else if (t == 3) val = aW[(size_t)l * 16384 + k * 128 + nn];
            else {
                const float* Wm = (t == 1) ? Wk : Wv;
                const float* R  = (t == 1) ? a_rel : m_rel;
                int h = nn >> 4, eo = nn & 15;
                float s = 0.f;
                #pragma unroll
                for (int d = 0; d < 16; ++d)
                    s += Wm[(size_t)l * 16384 + k * 128 + h * 16 + d] * R[((l * 8 + h) * 16 + d) * 16 + eo];
                val = s;
            }
        } else {
            int e2 = e - 131072;
            int nn = e2 >> 7, k = e2 & 127;
            val = fcW[k * 64 + nn];
        }
        g_bt[e] = __float2half(val);
    }
}

// ---------------- CSR build (stream B) ----------------
__global__ void init_kernel(const int* ei_words) {
    int gi = blockIdx.x * blockDim.x + threadIdx.x;
    if (gi < N_NODES) { g_counts[gi] = 0; g_fill[gi] = 0; }
    if (blockIdx.x == 0) {
        __shared__ int any;
        if (threadIdx.x == 0) any = 0;
        __syncthreads();
        int v = 0;
        for (int i = threadIdx.x; i < 2048; i += 256) v |= ei_words[2 * i + 1];
        if (v) atomicOr(&any, 1);
        __syncthreads();
        if (threadIdx.x == 0) g_use64 = (any == 0) ? 1 : 0;
    }
}

__global__ void hist_kernel(const void* ei) {
    int e = blockIdx.x * blockDim.x + threadIdx.x;
    if (e < N_EDGES) atomicAdd(&g_counts[ld_idx(ei, (long long)N_EDGES + e)], 1);
}

__global__ __launch_bounds__(256) void scan1_kernel() {
    __shared__ int wtot[8], woff[8];
    int tid = threadIdx.x;
    int gi = blockIdx.x * 256 + tid;
    int v = (gi < N_NODES) ? g_counts[gi] : 0;
    int x = v;
    #pragma unroll
    for (int o = 1; o < 32; o <<= 1) {
        int t = __shfl_up_sync(0xffffffffu, x, o);
        if ((tid & 31) >= o) x += t;
    }
    if ((tid & 31) == 31) wtot[tid >> 5] = x;
    __syncthreads();
    if (tid < 8) {
        int w = wtot[tid]; int y = w;
        #pragma unroll
        for (int o = 1; o < 8; o <<= 1) {
            int t = __shfl_up_sync(0xffu, y, o);
            if (tid >= o) y += t;
        }
        woff[tid] = y - w;
        if (tid == 7) g_bsums[blockIdx.x] = y;
    }
    __syncthreads();
    if (gi < N_NODES) g_rowptr[gi] = x - v + woff[tid >> 5];
}

__global__ __launch_bounds__(256) void scan2_kernel() {
    __shared__ int wtot[8], woff[8];
    int tid = threadIdx.x;
    int v = (tid < NB_SCAN) ? g_bsums[tid] : 0;
    int x = v;
    #pragma unroll
    for (int o = 1; o < 32; o <<= 1) {
        int t = __shfl_up_sync(0xffffffffu, x, o);
        if ((tid & 31) >= o) x += t;
    }
    if ((tid & 31) == 31) wtot[tid >> 5] = x;
    __syncthreads();
    if (tid < 8) {
        int w = wtot[tid]; int y = w;
        #pragma unroll
        for (int o = 1; o < 8; o <<= 1) {
            int t = __shfl_up_sync(0xffu, y, o);
            if (tid >= o) y += t;
        }
        woff[tid] = y - w;
    }
    __syncthreads();
    if (tid < NB_SCAN) g_bsums[tid] = x - v + woff[tid >> 5];
    if (tid == 255) g_rowptr[N_NODES] = x + woff[7];
}

__global__ void scan3_kernel() {
    int gi = blockIdx.x * blockDim.x + threadIdx.x;
    if (gi < N_NODES) g_rowptr[gi] += g_bsums[blockIdx.x];
}

__global__ void scatter_kernel(const void* ei) {
    int e = blockIdx.x * blockDim.x + threadIdx.x;
    if (e < N_EDGES) {
        int d = ld_idx(ei, (long long)N_EDGES + e);
        int s = ld_idx(ei, e);
        g_colsrc[g_rowptr[d] + atomicAdd(&g_fill[d], 1)] = s;
    }
}

// ---------------- gemm core: CTA 64m x NTn, 4 warps; optional h->smem park ----------------
template<int NT>
__device__ __forceinline__ void gemm_core(char* sm,
    const __half* __restrict__ A16, const __half* __restrict__ btile,
    const float* __restrict__ bias,
    float* C32, int c32s, __half* C16, int c16s,
    int mode, const float* skip, const __half* skip16,
    const float* gate, int m0, int park_h) {
    constexpr int NB2 = NT / 32;
    constexpr uint32_t BOFF = 64 * 272;
    uint32_t sbase = smem_u32(sm);
    int tid = threadIdx.x, wid = tid >> 5, lane = tid & 31;

    const __half* asrc = A16 + (size_t)m0 * 128;
    #pragma unroll
    for (int i = tid; i < 1024; i += 128) {
        int row = i >> 4, kc = i & 15;
        cp_async16(sbase + row * 272 + kc * 16, asrc + row * 128 + kc * 8);
    }
    #pragma unroll
    for (int i = tid; i < NT * 16; i += 128) {
        int row = i >> 4, kc = i & 15;
        cp_async16(sbase + BOFF + row * 272 + kc * 16, btile + row * 128 + kc * 8);
    }
    cp_async_wait_all();
    __syncthreads();

    int wm = wid & 1, wn = wid >> 1;
    uint32_t arowoff[2];
    #pragma unroll
    for (int mb = 0; mb < 2; ++mb) {
        int arow = wm * 32 + mb * 16 + (lane & 15);
        arowoff[mb] = (uint32_t)arow * 272u + (uint32_t)(lane & 16);
    }
    uint32_t browoff[NB2];
    #pragma unroll
    for (int nb2 = 0; nb2 < NB2; ++nb2) {
        int brow = wn * (NT / 2) + nb2 * 16 + (lane & 7) + ((lane & 16) >> 1);
        browoff[nb2] = (uint32_t)brow * 272u + (uint32_t)((lane & 8) << 1);
    }

    float acc[2][2 * NB2][4];
    #pragma unroll
    for (int mb = 0; mb < 2; ++mb)
        #pragma unroll
        for (int nb = 0; nb < 2 * NB2; ++nb)
            #pragma unroll
            for (int j = 0; j < 4; ++j) acc[mb][nb][j] = 0.0f;

    #pragma unroll
    for (int ks = 0; ks < 8; ++ks) {
        uint32_t kb = (uint32_t)ks * 32u;
        uint32_t a[2][4];
        ldsm4(a[0], sbase + arowoff[0] + kb);
        ldsm4(a[1], sbase + arowoff[1] + kb);
        #pragma unroll
        for (int nb2 = 0; nb2 < NB2; ++nb2) {
            uint32_t bb[4];
            ldsm4(bb, sbase + BOFF + browoff[nb2] + kb);
            mma16816(acc[0][2 * nb2],     a[0], bb[0], bb[1]);
            mma16816(acc[1][2 * nb2],     a[1], bb[0], bb[1]);
            mma16816(acc[0][2 * nb2 + 1], a[0], bb[2], bb[3]);
            mma16816(acc[1][2 * nb2 + 1], a[1], bb[2], bb[3]);
        }
    }

    if (park_h) __syncthreads();   // all mma/B reads done before park overwrites A region

    float beta = 0.f, ombeta = 0.f;
    if (mode == 1) {
        float g = gate[0];
        beta = 1.f / (1.f + expf(-g));
        ombeta = 1.f - beta;
    }
    int quad = lane >> 2, qt = lane & 3;
    int n0 = wn * (NT / 2);
    #pragma unroll
    for (int mb = 0; mb < 2; ++mb)
        #pragma unroll
        for (int half = 0; half < 2; ++half) {
            int lr = wm * 32 + mb * 16 + quad + half * 8;
            int grow = m0 + lr;
            #pragma unroll
            for (int nb = 0; nb < 2 * NB2; ++nb) {
                int col = n0 + nb * 8 + qt * 2;
                float v0 = acc[mb][nb][2 * half + 0] + bias[col + 0];
                float v1 = acc[mb][nb][2 * half + 1] + bias[col + 1];
                if (mode == 1) {
                    float sx, sy;
                    if (skip) {
                        float2 sv = *(const float2*)(skip + (size_t)grow * 128 + col);
                        sx = sv.x; sy = sv.y;
                    } else {
                        __half2 sh = *(const __half2*)(skip16 + (size_t)grow * 128 + col);
                        sx = __low2float(sh); sy = __high2float(sh);
                    }
                    v0 = fmaxf(beta * v0 + ombeta * sx, 0.f);
                    v1 = fmaxf(beta * v1 + ombeta * sy, 0.f);
                }
                if (C32) {
                    float2 o; o.x = v0; o.y = v1;
                    *(float2*)(C32 + (size_t)grow * c32s + col) = o;
                }
                if (C16)
                    *(__half2*)(C16 + (size_t)grow * c16s + col) = __floats2half2_rn(v0, v1);
                if (park_h)
                    *(__half2*)(sm + lr * 272 + col * 2) = __floats2half2_rn(v0, v1);
            }
        }
}

// second-stage gemm: A = parked h at sm[0..), B at sm + 64*272 (standard regions only)
template<int NTn>
__device__ __forceinline__ void gemm_from_parked(char* sm, const float* __restrict__ bias,
                                                 __half* __restrict__ C16, int c16s,
                                                 float* __restrict__ C32, int c32s,
                                                 const float* __restrict__ cbias32,
                                                 int m0) {
    constexpr int NB2 = NTn / 32;
    uint32_t sbase = smem_u32(sm);
    int tid = threadIdx.x, wid = tid >> 5, lane = tid & 31;
    int wm = wid & 1, wn = wid >> 1;
    uint32_t arowoff[2];
    #pragma unroll
    for (int mb = 0; mb < 2; ++mb) {
        int arow = wm * 32 + mb * 16 + (lane & 15);
        arowoff[mb] = (uint32_t)arow * 272u + (uint32_t)(lane & 16);
    }
    uint32_t browoff[NB2];
    #pragma unroll
    for (int nb2 = 0; nb2 < NB2; ++nb2) {
        int brow = wn * (NTn / 2) + nb2 * 16 + (lane & 7) + ((lane & 16) >> 1);
        browoff[nb2] = (uint32_t)brow * 272u + (uint32_t)((lane & 8) << 1);
    }
    float acc[2][2 * NB2][4];
    #pragma unroll
    for (int mb = 0; mb < 2; ++mb)
        #pragma unroll
        for (int nb = 0; nb < 2 * NB2; ++nb)
            #pragma unroll
            for (int j = 0; j < 4; ++j) acc[mb][nb][j] = 0.0f;
    #pragma unroll
    for (int ks = 0; ks < 8; ++ks) {
        uint32_t kb = (uint32_t)ks * 32u;
        uint32_t a[2][4];
        ldsm4(a[0], sbase + arowoff[0] + kb);
        ldsm4(a[1], sbase + arowoff[1] + kb);
        #pragma unroll
        for (int nb2 = 0; nb2 < NB2; ++nb2) {
            uint32_t bb[4];
            ldsm4(bb, sbase + 64 * 272 + browoff[nb2] + kb);
            mma16816(acc[0][2 * nb2],     a[0], bb[0], bb[1]);
            mma16816(acc[1][2 * nb2],     a[1], bb[0], bb[1]);
            mma16816(acc[0][2 * nb2 + 1], a[0], bb[2], bb[3]);
            mma16816(acc[1][2 * nb2 + 1], a[1], bb[2], bb[3]);
        }
    }
    int quad = lane >> 2, qt = lane & 3;
    int n0 = wn * (NTn / 2);
    #pragma unroll
    for (int mb = 0; mb < 2; ++mb)
        #pragma unroll
        for (int half = 0; half < 2; ++half) {
            int grow = m0 + wm * 32 + mb * 16 + quad + half * 8;
            #pragma unroll
            for (int nb = 0; nb < 2 * NB2; ++nb) {
                int col = n0 + nb * 8 + qt * 2;
                if (C16) {
                    float v0 = acc[mb][nb][2 * half + 0] + bias[col + 0];
                    float v1 = acc[mb][nb][2 * half + 1] + bias[col + 1];
                    *(__half2*)(C16 + (size_t)grow * c16s + col) = __floats2half2_rn(v0, v1);
                }
                if (C32) {
                    float2 o;
                    o.x = acc[mb][nb][2 * half + 0] + cbias32[col + 0];
                    o.y = acc[mb][nb][2 * half + 1] + cbias32[col + 1];
                    *(float2*)(C32 + (size_t)grow * c32s + col) = o;
                }
            }
        }
}

// ---------------- GEMM kernels ----------------
__global__ __launch_bounds__(128, 4)
void qkv_kernel(int l) {
    extern __shared__ char sm[];
    int bx = blockIdx.x;
    gemm_core<128>(sm, g_a16, g_bt + (size_t)(l * 4 + bx) * 16384,
                   g_bqkv + l * NQKV + bx * 128,
                   nullptr, 0, g_qkv16 + bx * 128, NQKV,
                   0, nullptr, nullptr, nullptr, blockIdx.y * 64, 0);
}

// fused aw0 + qkv1: aw layer-0 gemm (parks h, writes a16), then 3 layer-1 QKV
// tiles computed in-CTA from the parked h.
__global__ __launch_bounds__(128, 3)
void aw_qkv_kernel(const float* __restrict__ ab,
                   const float* __restrict__ skipsrc, const float* __restrict__ gate) {
    extern __shared__ char sm[];
    uint32_t sbase = smem_u32(sm);
    int tid = threadIdx.x;
    int m0 = blockIdx.y * 64;

    // aw0: A=agg16, B=tile3; park h into A region; also write a16 (layer-1 skip)
    gemm_core<128>(sm, g_agg16, g_bt + (size_t)3 * 16384, ab,
                   nullptr, 0, g_a16, CCH,
                   1, skipsrc, nullptr, gate, m0, 1);

    // qkv1: 3 col tiles from parked h
    for (int bx = 0; bx < 3; ++bx) {
        __syncthreads();   // parks visible / prior B reads done
        const __half* bsrc = g_bt + (size_t)(4 + bx) * 16384;
        #pragma unroll
        for (int i = tid; i < 2048; i += 128) {
            int row = i >> 4, kc = i & 15;
            cp_async16(sbase + 64 * 272 + row * 272 + kc * 16, bsrc + row * 128 + kc * 8);
        }
        cp_async_wait_all();
        __syncthreads();
        gemm_from_parked<128>(sm, g_bqkv + NQKV + bx * 128,
                              g_qkv16 + bx * 128, NQKV, nullptr, 0, nullptr, m0);
    }
}

// fused aw1 + fc: aw gemm parks h at sm[0..), then fc B tile loaded into the
// STANDARD B region (sm + 64*272) and fc computed from parked h. No aliasing.
__global__ __launch_bounds__(128, 4)
void aw_fc_kernel(const float* __restrict__ ab, const float* __restrict__ gate,
                  const float* __restrict__ fcb, float* __restrict__ out) {
    extern __shared__ char sm[];
    uint32_t sbase = smem_u32(sm);
    int tid = threadIdx.x;
    int m0 = blockIdx.y * 64;

    gemm_core<128>(sm, g_agg16, g_bt + (size_t)7 * 16384, ab,
                   nullptr, 0, nullptr, 0, 1, nullptr, g_a16, gate, m0, 1);
    __syncthreads();   // parks visible; all prior B reads complete

    {
        const __half* fsrc = g_bt + (size_t)8 * 16384;
        #pragma unroll
        for (int i = tid; i < 1024; i += 128) {
            int row = i >> 4, kc = i & 15;
            cp_async16(sbase + 64 * 272 + row * 272 + kc * 16, fsrc + row * 128 + kc * 8);
        }
        cp_async_wait_all();
    }
    __syncthreads();
    gemm_from_parked<64>(sm, nullptr, nullptr, 0, out, 64, fcb, m0);
}

// ---------------- edge kernel: 2 edges/warp-iter, 16 lanes/edge, 2x pipelined ----------------
__global__ __launch_bounds__(256)
void edge_kernel() {
    int tid = threadIdx.x, wid = tid >> 5, lane = tid & 31;
    int node = blockIdx.x * 8 + wid;
    int sub = lane >> 4, j = lane & 15;

    float q[8];
    {
        uint4 qraw = *(const uint4*)(g_qkv16 + (size_t)node * NQKV + 8 * j);
        const __half2* qh = (const __half2*)&qraw;
        #pragma unroll
        for (int t = 0; t < 4; ++t) {
            q[2 * t]     = __low2float(qh[t]);
            q[2 * t + 1] = __high2float(qh[t]);
        }
    }
    int p0 = g_rowptr[node], p1 = g_rowptr[node + 1];
    float s = 0.f;
    float acc[8];
    #pragma unroll
    for (int t = 0; t < 8; ++t) acc[t] = 0.f;

    int iters = (p1 - p0 + 1) >> 1;
    for (int it = 0; it < iters; it += 2) {
        int pA = p0 + 2 * it + sub;
        int pB = pA + 2;
        bool vA = pA < p1;
        bool vB = (it + 1 < iters) && (pB < p1);
        int snA = g_colsrc[vA ? pA : p0];
        int snB = g_colsrc[vB ? pB : p0];
        const __half* baseA = g_qkv16 + (size_t)snA * NQKV;
        const __half* baseB = g_qkv16 + (size_t)snB * NQKV;
        uint4 kA = *(const uint4*)(baseA + CCH + 8 * j);
        uint4 vA_ = *(const uint4*)(baseA + 2 * CCH + 8 * j);
        uint4 kB = *(const uint4*)(baseB + CCH + 8 * j);
        uint4 vB_ = *(const uint4*)(baseB + 2 * CCH + 8 * j);
        {
            const __half2* kh = (const __half2*)&kA;
            const __half2* vh = (const __half2*)&vA_;
            float d = 0.f;
            #pragma unroll
            for (int t = 0; t < 4; ++t)
                d += q[2 * t] * __low2float(kh[t]) + q[2 * t + 1] * __high2float(kh[t]);
            d += __shfl_xor_sync(0xffffffffu, d, 1);
            float e = vA ? __expf(d) : 0.f;
            s += e;
            #pragma unroll
            for (int t = 0; t < 4; ++t) {
                acc[2 * t]     = fmaf(e, __low2float(vh[t]), acc[2 * t]);
                acc[2 * t + 1] = fmaf(e, __high2float(vh[t]), acc[2 * t + 1]);
            }
        }
        {
            const __half2* kh = (const __half2*)&kB;
            const __half2* vh = (const __half2*)&vB_;
            float d = 0.f;
            #pragma unroll
            for (int t = 0; t < 4; ++t)
                d += q[2 * t] * __low2float(kh[t]) + q[2 * t + 1] * __high2float(kh[t]);
            d += __shfl_xor_sync(0xffffffffu, d, 1);
            float e = vB ? __expf(d) : 0.f;
            s += e;
            #pragma unroll
            for (int t = 0; t < 4; ++t) {
                acc[2 * t]     = fmaf(e, __low2float(vh[t]), acc[2 * t]);
                acc[2 * t + 1] = fmaf(e, __high2float(vh[t]), acc[2 * t + 1]);
            }
        }
    }

    s += __shfl_xor_sync(0xffffffffu, s, 16);
    #pragma unroll
    for (int t = 0; t < 8; ++t)
        acc[t] += __shfl_xor_sync(0xffffffffu, acc[t], 16);

    if (sub == 0) {
        float inv = 1.f / (s + 1e-16f);
        __half2 o[4];
        #pragma unroll
        for (int t = 0; t < 4; ++t)
            o[t] = __floats2half2_rn(gelu_tanh(acc[2 * t] * inv),
                                     gelu_tanh(acc[2 * t + 1] * inv));
        *(uint4*)(g_agg16 + (size_t)node * CCH + 8 * j) = *(uint4*)o;
    }
}

// ---------------- host launch ----------------
#define SMEM_G128 (64 * 272 + 128 * 272)       // 52224

extern "C" void kernel_launch(void* const* d_in, const int* in_sizes, int n_in,
                              void* d_out, int out_size) {
    const float* x    = (const float*)d_in[0];
    const void*  ei   = d_in[1];
    const float* Wk   = (const float*)d_in[2];
    const float* bk   = (const float*)d_in[3];
    const float* Wq   = (const float*)d_in[4];
    const float* bq   = (const float*)d_in[5];
    const float* Wv   = (const float*)d_in[6];
    const float* bv   = (const float*)d_in[7];
    const float* a_rel = (const float*)d_in[8];
    const float* m_rel = (const float*)d_in[9];
    const float* p_rel = (const float*)d_in[10];
    const float* skip  = (const float*)d_in[11];
    const float* aW    = (const float*)d_in[12];
    const float* ab    = (const float*)d_in[13];
    const float* fcW   = (const float*)d_in[14];
    const float* fcb   = (const float*)d_in[15];
    float* out = (float*)d_out;

    static cudaStream_t sB = nullptr;
    static cudaEvent_t eFork = nullptr, eJoin = nullptr;
    if (!sB) {
        cudaStreamCreateWithFlags(&sB, cudaStreamNonBlocking);
        cudaEventCreateWithFlags(&eFork, cudaEventDisableTiming);
        cudaEventCreateWithFlags(&eJoin, cudaEventDisableTiming);
        cudaFuncSetAttribute(qkv_kernel,    cudaFuncAttributeMaxDynamicSharedMemorySize, SMEM_G128);
        cudaFuncSetAttribute(aw_qkv_kernel, cudaFuncAttributeMaxDynamicSharedMemorySize, SMEM_G128);
        cudaFuncSetAttribute(aw_fc_kernel,  cudaFuncAttributeMaxDynamicSharedMemorySize, SMEM_G128);
    }

    // Fork: CSR chain on stream B; prep + qkv0 on main (independent until edge0).
    cudaEventRecord(eFork, 0);
    cudaStreamWaitEvent(sB, eFork, 0);

    init_kernel<<<NB_SCAN, 256, 0, sB>>>((const int*)ei);
    hist_kernel<<<(N_EDGES + 255) / 256, 256, 0, sB>>>(ei);
    scan1_kernel<<<NB_SCAN, 256, 0, sB>>>();
    scan2_kernel<<<1, 256, 0, sB>>>();
    scan3_kernel<<<NB_SCAN, 256, 0, sB>>>();
    scatter_kernel<<<(N_EDGES + 255) / 256, 256, 0, sB>>>(ei);
    cudaEventRecord(eJoin, sB);

    prep_main<<<PMAIN_BLKS, 256>>>(x, Wk, bk, Wq, bq, Wv, bv,
                                   a_rel, m_rel, p_rel, aW, fcW);
    qkv_kernel<<<dim3(3, 625), 128, SMEM_G128>>>(0);

    cudaStreamWaitEvent(0, eJoin, 0);

    edge_kernel<<<5000, 256>>>();
    // fused aw0 + qkv1 (h parked in smem; a16 gets h1 fp16 for the aw_fc skip)
    aw_qkv_kernel<<<dim3(1, 625), 128, SMEM_G128>>>(ab, x, skip);
    edge_kernel<<<5000, 256>>>();
    // fused aw1 + fc
    aw_fc_kernel<<<dim3(1, 625), 128, SMEM_G128>>>(ab + CCH, skip + 1, fcb, out);
}

// round 17
// speedup vs baseline: 1.1730x; 1.0005x over previous
#include <cuda_runtime.h>
#include <cuda_fp16.h>
#include <math.h>
#include <stdint.h>

#define N_NODES 40000
#define N_PAD   40064
#define N_EDGES 640000
#define CCH 128
#define NQKV 384
#define NB_SCAN 157

// prep_main block ranges
#define BIASB  3
#define CVTB   10016           // N_PAD*64 / 256 exact
#define PREPB  544             // 139264 / 256
#define PMAIN_BLKS (BIASB + CVTB + PREPB)

// ---------------- device scratch ----------------
__device__ __half g_a16[(size_t)N_PAD * CCH];       // x fp16; holds h1 fp16 after aw0 (skip for aw_fc)
__device__ __half g_qkv16[(size_t)N_PAD * NQKV];
__device__ __half g_agg16[(size_t)N_PAD * CCH];
__device__ int    g_rowptr[N_NODES + 1];
__device__ int    g_colsrc[N_EDGES];
__device__ int    g_counts[N_NODES];
__device__ int    g_fill[N_NODES];
__device__ int    g_bsums[256];
__device__ float  g_bqkv[2 * NQKV];
__device__ __half g_bt[139264];
__device__ int    g_use64;

// ---------------- helpers ----------------
__device__ __forceinline__ uint32_t smem_u32(const void* p) {
    uint32_t a;
    asm("{ .reg .u64 t; cvta.to.shared.u64 t, %1; cvt.u32.u64 %0, t; }" : "=r"(a) : "l"(p));
    return a;
}
__device__ __forceinline__ void cp_async16(uint32_t dst, const void* src) {
    asm volatile("cp.async.ca.shared.global [%0], [%1], 16;" :: "r"(dst), "l"(src));
}
__device__ __forceinline__ void cp_async_wait_all() {
    asm volatile("cp.async.commit_group;");
    asm volatile("cp.async.wait_group 0;");
}
__device__ __forceinline__ int ld_idx(const void* ei, long long pos) {
    if (g_use64) return (int)((const long long*)ei)[pos];
    return ((const int*)ei)[pos];
}
__device__ __forceinline__ float gelu_tanh(float x) {
    float x3 = x * x * x;
    return 0.5f * x * (1.0f + tanhf(0.7978845608028654f * (x + 0.044715f * x3)));
}
__device__ __forceinline__ void ldsm4(uint32_t* r, uint32_t addr) {
    asm volatile("ldmatrix.sync.aligned.m8n8.x4.shared.b16 {%0,%1,%2,%3}, [%4];"
        : "=r"(r[0]), "=r"(r[1]), "=r"(r[2]), "=r"(r[3]) : "r"(addr));
}
__device__ __forceinline__ void mma16816(float* c, const uint32_t* a, uint32_t b0, uint32_t b1) {
    asm volatile("mma.sync.aligned.m16n8k16.row.col.f32.f16.f16.f32 "
        "{%0,%1,%2,%3}, {%4,%5,%6,%7}, {%8,%9}, {%0,%1,%2,%3};"
        : "+f"(c[0]), "+f"(c[1]), "+f"(c[2]), "+f"(c[3])
        : "r"(a[0]), "r"(a[1]), "r"(a[2]), "r"(a[3]), "r"(b0), "r"(b1));
}

// ---------------- prep_main: bias | cvt_x | prep_b(direct) ----------------
__global__ __launch_bounds__(256)
void prep_main(const float* __restrict__ x,
               const float* Wk, const float* bk, const float* Wq, const float* bq,
               const float* Wv, const float* bv,
               const float* a_rel, const float* m_rel, const float* p_rel,
               const float* aW, const float* fcW) {
    int b = blockIdx.x, tid = threadIdx.x;
    if (b < BIASB) {
        int idx = b * 256 + tid;
        if (idx < 768) {
            int l = idx / NQKV, c = idx % NQKV;
            int t = c >> 7, cc = c & 127, h = cc >> 4, eo = cc & 15;
            float bias;
            if (t == 0) bias = bq[l * 128 + cc] * p_rel[l * 8 + h] * 0.25f;
            else {
                const float* bm = (t == 1) ? bk : bv;
                const float* R  = (t == 1) ? a_rel : m_rel;
                float sb = 0.f;
                #pragma unroll
                for (int d = 0; d < 16; ++d)
                    sb += bm[l * 128 + h * 16 + d] * R[((l * 8 + h) * 16 + d) * 16 + eo];
                bias = sb;
            }
            g_bqkv[l * NQKV + c] = bias;
        }
        return;
    }
    b -= BIASB;
    if (b < CVTB) {
        int i = b * 256 + tid;
        if (i < N_NODES * 64) {
            float2 v = ((const float2*)x)[i];
            ((__half2*)g_a16)[i] = __floats2half2_rn(v.x, v.y);
        } else {
            ((__half2*)g_a16)[i] = __floats2half2_rn(0.f, 0.f);
        }
        return;
    }
    b -= CVTB;
    {
        int e = b * 256 + tid;
        float val;
        if (e < 131072) {
            int tile = e >> 14, within = e & 16383;
            int nn = within >> 7, k = within & 127;
            int l = tile >> 2, t = tile & 3;
            if (t == 0)      val = Wq[(size_t)l * 16384 + k * 128 + nn] * p_rel[l * 8 + (nn >> 4)] * 0.25f;
            else if (t == 3) val = aW[(size_t)l * 16384 + k * 128 + nn];
            else {
                const float* Wm = (t == 1) ? Wk : Wv;
                const float* R  = (t == 1) ? a_rel : m_rel;
                int h = nn >> 4, eo = nn & 15;
                float s = 0.f;
                #pragma unroll
                for (int d = 0; d < 16; ++d)
                    s += Wm[(size_t)l * 16384 + k * 128 + h * 16 + d] * R[((l * 8 + h) * 16 + d) * 16 + eo];
                val = s;
            }
        } else {
            int e2 = e - 131072;
            int nn = e2 >> 7, k = e2 & 127;
            val = fcW[k * 64 + nn];
        }
        g_bt[e] = __float2half(val);
    }
}

// ---------------- CSR build (stream B) ----------------
__global__ void init_kernel(const int* ei_words) {
    int gi = blockIdx.x * blockDim.x + threadIdx.x;
    if (gi < N_NODES) { g_counts[gi] = 0; g_fill[gi] = 0; }
    if (blockIdx.x == 0) {
        __shared__ int any;
        if (threadIdx.x == 0) any = 0;
        __syncthreads();
        int v = 0;
        for (int i = threadIdx.x; i < 2048; i += 256) v |= ei_words[2 * i + 1];
        if (v) atomicOr(&any, 1);
        __syncthreads();
        if (threadIdx.x == 0) g_use64 = (any == 0) ? 1 : 0;
    }
}

__global__ void hist_kernel(const void* ei) {
    int e = blockIdx.x * blockDim.x + threadIdx.x;
    if (e < N_EDGES) atomicAdd(&g_counts[ld_idx(ei, (long long)N_EDGES + e)], 1);
}

__global__ __launch_bounds__(256) void scan1_kernel() {
    __shared__ int wtot[8], woff[8];
    int tid = threadIdx.x;
    int gi = blockIdx.x * 256 + tid;
    int v = (gi < N_NODES) ? g_counts[gi] : 0;
    int x = v;
    #pragma unroll
    for (int o = 1; o < 32; o <<= 1) {
        int t = __shfl_up_sync(0xffffffffu, x, o);
        if ((tid & 31) >= o) x += t;
    }
    if ((tid & 31) == 31) wtot[tid >> 5] = x;
    __syncthreads();
    if (tid < 8) {
        int w = wtot[tid]; int y = w;
        #pragma unroll
        for (int o = 1; o < 8; o <<= 1) {
            int t = __shfl_up_sync(0xffu, y, o);
            if (tid >= o) y += t;
        }
        woff[tid] = y - w;
        if (tid == 7) g_bsums[blockIdx.x] = y;
    }
    __syncthreads();
    if (gi < N_NODES) g_rowptr[gi] = x - v + woff[tid >> 5];
}

__global__ __launch_bounds__(256) void scan2_kernel() {
    __shared__ int wtot[8], woff[8];
    int tid = threadIdx.x;
    int v = (tid < NB_SCAN) ? g_bsums[tid] : 0;
    int x = v;
    #pragma unroll
    for (int o = 1; o < 32; o <<= 1) {
        int t = __shfl_up_sync(0xffffffffu, x, o);
        if ((tid & 31) >= o) x += t;
    }
    if ((tid & 31) == 31) wtot[tid >> 5] = x;
    __syncthreads();
    if (tid < 8) {
        int w = wtot[tid]; int y = w;
        #pragma unroll
        for (int o = 1; o < 8; o <<= 1) {
            int t = __shfl_up_sync(0xffu, y, o);
            if (tid >= o) y += t;
        }
        woff[tid] = y - w;
    }
    __syncthreads();
    if (tid < NB_SCAN) g_bsums[tid] = x - v + woff[tid >> 5];
    if (tid == 255) g_rowptr[N_NODES] = x + woff[7];
}

__global__ void scan3_kernel() {
    int gi = blockIdx.x * blockDim.x + threadIdx.x;
    if (gi < N_NODES) g_rowptr[gi] += g_bsums[blockIdx.x];
}

__global__ void scatter_kernel(const void* ei) {
    int e = blockIdx.x * blockDim.x + threadIdx.x;
    if (e < N_EDGES) {
        int d = ld_idx(ei, (long long)N_EDGES + e);
        int s = ld_idx(ei, e);
        g_colsrc[g_rowptr[d] + atomicAdd(&g_fill[d], 1)] = s;
    }
}

// ---------------- gemm core: CTA 64m x NTn, 4 warps; optional h->smem park ----------------
template<int NT>
__device__ __forceinline__ void gemm_core(char* sm,
    const __half* __restrict__ A16, const __half* __restrict__ btile,
    const float* __restrict__ bias,
    float* C32, int c32s, __half* C16, int c16s,
    int mode, const float* skip, const __half* skip16,
    const float* gate, int m0, int park_h) {
    constexpr int NB2 = NT / 32;
    constexpr uint32_t BOFF = 64 * 272;
    uint32_t sbase = smem_u32(sm);
    int tid = threadIdx.x, wid = tid >> 5, lane = tid & 31;

    const __half* asrc = A16 + (size_t)m0 * 128;
    #pragma unroll
    for (int i = tid; i < 1024; i += 128) {
        int row = i >> 4, kc = i & 15;
        cp_async16(sbase + row * 272 + kc * 16, asrc + row * 128 + kc * 8);
    }
    #pragma unroll
    for (int i = tid; i < NT * 16; i += 128) {
        int row = i >> 4, kc = i & 15;
        cp_async16(sbase + BOFF + row * 272 + kc * 16, btile + row * 128 + kc * 8);
    }
    cp_async_wait_all();
    __syncthreads();

    int wm = wid & 1, wn = wid >> 1;
    uint32_t arowoff[2];
    #pragma unroll
    for (int mb = 0; mb < 2; ++mb) {
        int arow = wm * 32 + mb * 16 + (lane & 15);
        arowoff[mb] = (uint32_t)arow * 272u + (uint32_t)(lane & 16);
    }
    uint32_t browoff[NB2];
    #pragma unroll
    for (int nb2 = 0; nb2 < NB2; ++nb2) {
        int brow = wn * (NT / 2) + nb2 * 16 + (lane & 7) + ((lane & 16) >> 1);
        browoff[nb2] = (uint32_t)brow * 272u + (uint32_t)((lane & 8) << 1);
    }

    float acc[2][2 * NB2][4];
    #pragma unroll
    for (int mb = 0; mb < 2; ++mb)
        #pragma unroll
        for (int nb = 0; nb < 2 * NB2; ++nb)
            #pragma unroll
            for (int j = 0; j < 4; ++j) acc[mb][nb][j] = 0.0f;

    #pragma unroll
    for (int ks = 0; ks < 8; ++ks) {
        uint32_t kb = (uint32_t)ks * 32u;
        uint32_t a[2][4];
        ldsm4(a[0], sbase + arowoff[0] + kb);
        ldsm4(a[1], sbase + arowoff[1] + kb);
        #pragma unroll
        for (int nb2 = 0; nb2 < NB2; ++nb2) {
            uint32_t bb[4];
            ldsm4(bb, sbase + BOFF + browoff[nb2] + kb);
            mma16816(acc[0][2 * nb2],     a[0], bb[0], bb[1]);
            mma16816(acc[1][2 * nb2],     a[1], bb[0], bb[1]);
            mma16816(acc[0][2 * nb2 + 1], a[0], bb[2], bb[3]);
            mma16816(acc[1][2 * nb2 + 1], a[1], bb[2], bb[3]);
        }
    }

    if (park_h) __syncthreads();   // all mma/B reads done before park overwrites A region

    float beta = 0.f, ombeta = 0.f;
    if (mode == 1) {
        float g = gate[0];
        beta = 1.f / (1.f + expf(-g));
        ombeta = 1.f - beta;
    }
    int quad = lane >> 2, qt = lane & 3;
    int n0 = wn * (NT / 2);
    #pragma unroll
    for (int mb = 0; mb < 2; ++mb)
        #pragma unroll
        for (int half = 0; half < 2; ++half) {
            int lr = wm * 32 + mb * 16 + quad + half * 8;
            int grow = m0 + lr;
            #pragma unroll
            for (int nb = 0; nb < 2 * NB2; ++nb) {
                int col = n0 + nb * 8 + qt * 2;
                float v0 = acc[mb][nb][2 * half + 0] + bias[col + 0];
                float v1 = acc[mb][nb][2 * half + 1] + bias[col + 1];
                if (mode == 1) {
                    float sx, sy;
                    if (skip) {
                        float2 sv = *(const float2*)(skip + (size_t)grow * 128 + col);
                        sx = sv.x; sy = sv.y;
                    } else {
                        __half2 sh = *(const __half2*)(skip16 + (size_t)grow * 128 + col);
                        sx = __low2float(sh); sy = __high2float(sh);
                    }
                    v0 = fmaxf(beta * v0 + ombeta * sx, 0.f);
                    v1 = fmaxf(beta * v1 + ombeta * sy, 0.f);
                }
                if (C32) {
                    float2 o; o.x = v0; o.y = v1;
                    *(float2*)(C32 + (size_t)grow * c32s + col) = o;
                }
                if (C16)
                    *(__half2*)(C16 + (size_t)grow * c16s + col) = __floats2half2_rn(v0, v1);
                if (park_h)
                    *(__half2*)(sm + lr * 272 + col * 2) = __floats2half2_rn(v0, v1);
            }
        }
}

// second-stage gemm: A = parked h at sm[0..), B at sm + 64*272 (standard regions only)
template<int NTn>
__device__ __forceinline__ void gemm_from_parked(char* sm, const float* __restrict__ bias,
                                                 __half* __restrict__ C16, int c16s,
                                                 float* __restrict__ C32, int c32s,
                                                 const float* __restrict__ cbias32,
                                                 int m0) {
    constexpr int NB2 = NTn / 32;
    uint32_t sbase = smem_u32(sm);
    int tid = threadIdx.x, wid = tid >> 5, lane = tid & 31;
    int wm = wid & 1, wn = wid >> 1;
    uint32_t arowoff[2];
    #pragma unroll
    for (int mb = 0; mb < 2; ++mb) {
        int arow = wm * 32 + mb * 16 + (lane & 15);
        arowoff[mb] = (uint32_t)arow * 272u + (uint32_t)(lane & 16);
    }
    uint32_t browoff[NB2];
    #pragma unroll
    for (int nb2 = 0; nb2 < NB2; ++nb2) {
        int brow = wn * (NTn / 2) + nb2 * 16 + (lane & 7) + ((lane & 16) >> 1);
        browoff[nb2] = (uint32_t)brow * 272u + (uint32_t)((lane & 8) << 1);
    }
    float acc[2][2 * NB2][4];
    #pragma unroll
    for (int mb = 0; mb < 2; ++mb)
        #pragma unroll
        for (int nb = 0; nb < 2 * NB2; ++nb)
            #pragma unroll
            for (int j = 0; j < 4; ++j) acc[mb][nb][j] = 0.0f;
    #pragma unroll
    for (int ks = 0; ks < 8; ++ks) {
        uint32_t kb = (uint32_t)ks * 32u;
        uint32_t a[2][4];
        ldsm4(a[0], sbase + arowoff[0] + kb);
        ldsm4(a[1], sbase + arowoff[1] + kb);
        #pragma unroll
        for (int nb2 = 0; nb2 < NB2; ++nb2) {
            uint32_t bb[4];
            ldsm4(bb, sbase + 64 * 272 + browoff[nb2] + kb);
            mma16816(acc[0][2 * nb2],     a[0], bb[0], bb[1]);
            mma16816(acc[1][2 * nb2],     a[1], bb[0], bb[1]);
            mma16816(acc[0][2 * nb2 + 1], a[0], bb[2], bb[3]);
            mma16816(acc[1][2 * nb2 + 1], a[1], bb[2], bb[3]);
        }
    }
    int quad = lane >> 2, qt = lane & 3;
    int n0 = wn * (NTn / 2);
    #pragma unroll
    for (int mb = 0; mb < 2; ++mb)
        #pragma unroll
        for (int half = 0; half < 2; ++half) {
            int grow = m0 + wm * 32 + mb * 16 + quad + half * 8;
            #pragma unroll
            for (int nb = 0; nb < 2 * NB2; ++nb) {
                int col = n0 + nb * 8 + qt * 2;
                if (C16) {
                    float v0 = acc[mb][nb][2 * half + 0] + bias[col + 0];
                    float v1 = acc[mb][nb][2 * half + 1] + bias[col + 1];
                    *(__half2*)(C16 + (size_t)grow * c16s + col) = __floats2half2_rn(v0, v1);
                }
                if (C32) {
                    float2 o;
                    o.x = acc[mb][nb][2 * half + 0] + cbias32[col + 0];
                    o.y = acc[mb][nb][2 * half + 1] + cbias32[col + 1];
                    *(float2*)(C32 + (size_t)grow * c32s + col) = o;
                }
            }
        }
}

// ---------------- GEMM kernels ----------------
__global__ __launch_bounds__(128, 4)
void qkv_kernel(int l) {
    extern __shared__ char sm[];
    int bx = blockIdx.x;
    gemm_core<128>(sm, g_a16, g_bt + (size_t)(l * 4 + bx) * 16384,
                   g_bqkv + l * NQKV + bx * 128,
                   nullptr, 0, g_qkv16 + bx * 128, NQKV,
                   0, nullptr, nullptr, nullptr, blockIdx.y * 64, 0);
}

// fused aw0 + qkv1: aw layer-0 gemm (parks h, writes a16), then 3 layer-1 QKV
// tiles computed in-CTA from the parked h.
__global__ __launch_bounds__(128, 3)
void aw_qkv_kernel(const float* __restrict__ ab,
                   const float* __restrict__ skipsrc, const float* __restrict__ gate) {
    extern __shared__ char sm[];
    uint32_t sbase = smem_u32(sm);
    int tid = threadIdx.x;
    int m0 = blockIdx.y * 64;

    // aw0: A=agg16, B=tile3; park h into A region; also write a16 (layer-1 skip)
    gemm_core<128>(sm, g_agg16, g_bt + (size_t)3 * 16384, ab,
                   nullptr, 0, g_a16, CCH,
                   1, skipsrc, nullptr, gate, m0, 1);

    // qkv1: 3 col tiles from parked h
    for (int bx = 0; bx < 3; ++bx) {
        __syncthreads();   // parks visible / prior B reads done
        const __half* bsrc = g_bt + (size_t)(4 + bx) * 16384;
        #pragma unroll
        for (int i = tid; i < 2048; i += 128) {
            int row = i >> 4, kc = i & 15;
            cp_async16(sbase + 64 * 272 + row * 272 + kc * 16, bsrc + row * 128 + kc * 8);
        }
        cp_async_wait_all();
        __syncthreads();
        gemm_from_parked<128>(sm, g_bqkv + NQKV + bx * 128,
                              g_qkv16 + bx * 128, NQKV, nullptr, 0, nullptr, m0);
    }
}

// fused aw1 + fc: aw gemm parks h at sm[0..), then fc B tile loaded into the
// STANDARD B region (sm + 64*272) and fc computed from parked h. No aliasing.
__global__ __launch_bounds__(128, 4)
void aw_fc_kernel(const float* __restrict__ ab, const float* __restrict__ gate,
                  const float* __restrict__ fcb, float* __restrict__ out) {
    extern __shared__ char sm[];
    uint32_t sbase = smem_u32(sm);
    int tid = threadIdx.x;
    int m0 = blockIdx.y * 64;

    gemm_core<128>(sm, g_agg16, g_bt + (size_t)7 * 16384, ab,
                   nullptr, 0, nullptr, 0, 1, nullptr, g_a16, gate, m0, 1);
    __syncthreads();   // parks visible; all prior B reads complete

    {
        const __half* fsrc = g_bt + (size_t)8 * 16384;
        #pragma unroll
        for (int i = tid; i < 1024; i += 128) {
            int row = i >> 4, kc = i & 15;
            cp_async16(sbase + 64 * 272 + row * 272 + kc * 16, fsrc + row * 128 + kc * 8);
        }
        cp_async_wait_all();
    }
    __syncthreads();
    gemm_from_parked<64>(sm, nullptr, nullptr, 0, out, 64, fcb, m0);
}

// ---------------- edge kernel: 2 edges/warp-iter, 16 lanes/edge, 2x pipelined ----------------
__global__ __launch_bounds__(256)
void edge_kernel() {
    int tid = threadIdx.x, wid = tid >> 5, lane = tid & 31;
    int node = blockIdx.x * 8 + wid;
    int sub = lane >> 4, j = lane & 15;

    float q[8];
    {
        uint4 qraw = *(const uint4*)(g_qkv16 + (size_t)node * NQKV + 8 * j);
        const __half2* qh = (const __half2*)&qraw;
        #pragma unroll
        for (int t = 0; t < 4; ++t) {
            q[2 * t]     = __low2float(qh[t]);
            q[2 * t + 1] = __high2float(qh[t]);
        }
    }
    int p0 = g_rowptr[node], p1 = g_rowptr[node + 1];
    float s = 0.f;
    float acc[8];
    #pragma unroll
    for (int t = 0; t < 8; ++t) acc[t] = 0.f;

    int iters = (p1 - p0 + 1) >> 1;
    for (int it = 0; it < iters; it += 2) {
        int pA = p0 + 2 * it + sub;
        int pB = pA + 2;
        bool vA = pA < p1;
        bool vB = (it + 1 < iters) && (pB < p1);
        int snA = g_colsrc[vA ? pA : p0];
        int snB = g_colsrc[vB ? pB : p0];
        const __half* baseA = g_qkv16 + (size_t)snA * NQKV;
        const __half* baseB = g_qkv16 + (size_t)snB * NQKV;
        uint4 kA = *(const uint4*)(baseA + CCH + 8 * j);
        uint4 vA_ = *(const uint4*)(baseA + 2 * CCH + 8 * j);
        uint4 kB = *(const uint4*)(baseB + CCH + 8 * j);
        uint4 vB_ = *(const uint4*)(baseB + 2 * CCH + 8 * j);
        {
            const __half2* kh = (const __half2*)&kA;
            const __half2* vh = (const __half2*)&vA_;
            float d = 0.f;
            #pragma unroll
            for (int t = 0; t < 4; ++t)
                d += q[2 * t] * __low2float(kh[t]) + q[2 * t + 1] * __high2float(kh[t]);
            d += __shfl_xor_sync(0xffffffffu, d, 1);
            float e = vA ? __expf(d) : 0.f;
            s += e;
            #pragma unroll
            for (int t = 0; t < 4; ++t) {
                acc[2 * t]     = fmaf(e, __low2float(vh[t]), acc[2 * t]);
                acc[2 * t + 1] = fmaf(e, __high2float(vh[t]), acc[2 * t + 1]);
            }
        }
        {
            const __half2* kh = (const __half2*)&kB;
            const __half2* vh = (const __half2*)&vB_;
            float d = 0.f;
            #pragma unroll
            for (int t = 0; t < 4; ++t)
                d += q[2 * t] * __low2float(kh[t]) + q[2 * t + 1] * __high2float(kh[t]);
            d += __shfl_xor_sync(0xffffffffu, d, 1);
            float e = vB ? __expf(d) : 0.f;
            s += e;
            #pragma unroll
            for (int t = 0; t < 4; ++t) {
                acc[2 * t]     = fmaf(e, __low2float(vh[t]), acc[2 * t]);
                acc[2 * t + 1] = fmaf(e, __high2float(vh[t]), acc[2 * t + 1]);
            }
        }
    }

    s += __shfl_xor_sync(0xffffffffu, s, 16);
    #pragma unroll
    for (int t = 0; t < 8; ++t)
        acc[t] += __shfl_xor_sync(0xffffffffu, acc[t], 16);

    if (sub == 0) {
        float inv = 1.f / (s + 1e-16f);
        __half2 o[4];
        #pragma unroll
        for (int t = 0; t < 4; ++t)
            o[t] = __floats2half2_rn(gelu_tanh(acc[2 * t] * inv),
                                     gelu_tanh(acc[2 * t + 1] * inv));
        *(uint4*)(g_agg16 + (size_t)node * CCH + 8 * j) = *(uint4*)o;
    }
}

// ---------------- host launch ----------------
#define SMEM_G128 (64 * 272 + 128 * 272)       // 52224

extern "C" void kernel_launch(void* const* d_in, const int* in_sizes, int n_in,
                              void* d_out, int out_size) {
    const float* x    = (const float*)d_in[0];
    const void*  ei   = d_in[1];
    const float* Wk   = (const float*)d_in[2];
    const float* bk   = (const float*)d_in[3];
    const float* Wq   = (const float*)d_in[4];
    const float* bq   = (const float*)d_in[5];
    const float* Wv   = (const float*)d_in[6];
    const float* bv   = (const float*)d_in[7];
    const float* a_rel = (const float*)d_in[8];
    const float* m_rel = (const float*)d_in[9];
    const float* p_rel = (const float*)d_in[10];
    const float* skip  = (const float*)d_in[11];
    const float* aW    = (const float*)d_in[12];
    const float* ab    = (const float*)d_in[13];
    const float* fcW   = (const float*)d_in[14];
    const float* fcb   = (const float*)d_in[15];
    float* out = (float*)d_out;

    static cudaStream_t sB = nullptr;
    static cudaEvent_t eFork = nullptr, eJoin = nullptr;
    if (!sB) {
        cudaStreamCreateWithFlags(&sB, cudaStreamNonBlocking);
        cudaEventCreateWithFlags(&eFork, cudaEventDisableTiming);
        cudaEventCreateWithFlags(&eJoin, cudaEventDisableTiming);
        cudaFuncSetAttribute(qkv_kernel,    cudaFuncAttributeMaxDynamicSharedMemorySize, SMEM_G128);
        cudaFuncSetAttribute(aw_qkv_kernel, cudaFuncAttributeMaxDynamicSharedMemorySize, SMEM_G128);
        cudaFuncSetAttribute(aw_fc_kernel,  cudaFuncAttributeMaxDynamicSharedMemorySize, SMEM_G128);
    }

    // Fork: CSR chain on stream B; prep + qkv0 on main (independent until edge0).
    cudaEventRecord(eFork, 0);
    cudaStreamWaitEvent(sB, eFork, 0);

    init_kernel<<<NB_SCAN, 256, 0, sB>>>((const int*)ei);
    hist_kernel<<<(N_EDGES + 255) / 256, 256, 0, sB>>>(ei);
    scan1_kernel<<<NB_SCAN, 256, 0, sB>>>();
    scan2_kernel<<<1, 256, 0, sB>>>();
    scan3_kernel<<<NB_SCAN, 256, 0, sB>>>();
    scatter_kernel<<<(N_EDGES + 255) / 256, 256, 0, sB>>>(ei);
    cudaEventRecord(eJoin, sB);

    prep_main<<<PMAIN_BLKS, 256>>>(x, Wk, bk, Wq, bq, Wv, bv,
                                   a_rel, m_rel, p_rel, aW, fcW);
    qkv_kernel<<<dim3(3, 625), 128, SMEM_G128>>>(0);

    cudaStreamWaitEvent(0, eJoin, 0);

    edge_kernel<<<5000, 256>>>();
    // fused aw0 + qkv1 (h parked in smem; a16 gets h1 fp16 for the aw_fc skip)
    aw_qkv_kernel<<<dim3(1, 625), 128, SMEM_G128>>>(ab, x, skip);
    edge_kernel<<<5000, 256>>>();
    // fused aw1 + fc
    aw_fc_kernel<<<dim3(1, 625), 128, SMEM_G128>>>(ab + CCH, skip + 1, fcb, out);
}